// round 2
// baseline (speedup 1.0000x reference)
#include <cuda_runtime.h>

// Problem constants
#define M_TOTAL (8 * 4096)   // 32768 rows
#define E_DIM   512
#define FFN_DIM 2048
#define NQ      8

// Scratch (device globals: allocation-free per harness rules)
__device__ float g_y1[(size_t)M_TOTAL * E_DIM];   // pre-LN1 (x + attn_out + b_comb)
__device__ float g_x1[(size_t)M_TOTAL * E_DIM];   // LN1 output
__device__ float g_y2[(size_t)M_TOTAL * E_DIM];   // pre-LN2 (x1 + ffn_out + b2)
__device__ float g_fq[(size_t)M_TOTAL * NQ];      // cos(x1[:, :8] + theta_ffn)

// ---------------- packed f32x2 helpers ----------------
__device__ __forceinline__ void fma2(unsigned long long &d,
                                     unsigned long long a,
                                     unsigned long long b) {
    asm("fma.rn.f32x2 %0, %1, %2, %0;" : "+l"(d) : "l"(a), "l"(b));
}
__device__ __forceinline__ unsigned long long pack2(float x) {
    unsigned long long r;
    asm("mov.b64 %0, {%1, %1};" : "=l"(r) : "f"(x));
    return r;
}
__device__ __forceinline__ float2 unpack2(unsigned long long v) {
    float2 r;
    asm("mov.b64 {%0, %1}, %2;" : "=f"(r.x), "=f"(r.y) : "l"(v));
    return r;
}

// ---------------- shared 128x128x16 micro-kernel ----------------
// As/Bs are [BK][BM(+pad)] transposed tiles. Each thread: 8 (m) x 8 (n) outputs,
// held as 8 x 4 packed f32x2 accumulators (pairs along n).
__device__ __forceinline__ void mma_tile(const float (&As)[16][132],
                                         const float (&Bs)[16][132],
                                         int tm, int tn,
                                         unsigned long long (&acc)[8][4]) {
#pragma unroll
    for (int k = 0; k < 16; ++k) {
        const float4 a0 = *(const float4 *)&As[k][tm];
        const float4 a1 = *(const float4 *)&As[k][tm + 4];
        const ulonglong2 bb0 = *(const ulonglong2 *)&Bs[k][tn];
        const ulonglong2 bb1 = *(const ulonglong2 *)&Bs[k][tn + 4];
        unsigned long long av[8];
        av[0] = pack2(a0.x); av[1] = pack2(a0.y);
        av[2] = pack2(a0.z); av[3] = pack2(a0.w);
        av[4] = pack2(a1.x); av[5] = pack2(a1.y);
        av[6] = pack2(a1.z); av[7] = pack2(a1.w);
        unsigned long long bv[4] = {bb0.x, bb0.y, bb1.x, bb1.y};
#pragma unroll
        for (int i = 0; i < 8; ++i)
#pragma unroll
            for (int j = 0; j < 4; ++j)
                fma2(acc[i][j], av[i], bv[j]);
    }
}

// ================= GEMM1 =================
// y1[m,n] = x[m,n] + bc[n] + sum_k cos(x[m,k] + th[k]) * Wc[n,k]
__global__ __launch_bounds__(256, 2) void gemm1_kernel(
    const float *__restrict__ x, const float *__restrict__ th,
    const float *__restrict__ Wc, const float *__restrict__ bc) {
    __shared__ float As[16][132];
    __shared__ float Bs[16][132];

    const int bm = blockIdx.x * 128;
    const int bn = blockIdx.y * 128;
    const int t = threadIdx.x;
    const int tm = (t >> 4) * 8;
    const int tn = (t & 15) * 8;
    const int r0 = t >> 2;            // 0..63
    const int q0 = (t & 3) * 4;       // 0,4,8,12

    unsigned long long acc[8][4];
#pragma unroll
    for (int i = 0; i < 8; ++i)
#pragma unroll
        for (int j = 0; j < 4; ++j) acc[i][j] = 0ull;

    for (int k0 = 0; k0 < E_DIM; k0 += 16) {
#pragma unroll
        for (int p = 0; p < 2; ++p) {
            const int row = r0 + p * 64;
            float4 v = *(const float4 *)(x + (size_t)(bm + row) * E_DIM + k0 + q0);
            As[q0 + 0][row] = cosf(v.x + th[k0 + q0 + 0]);
            As[q0 + 1][row] = cosf(v.y + th[k0 + q0 + 1]);
            As[q0 + 2][row] = cosf(v.z + th[k0 + q0 + 2]);
            As[q0 + 3][row] = cosf(v.w + th[k0 + q0 + 3]);
            float4 w = *(const float4 *)(Wc + (size_t)(bn + row) * E_DIM + k0 + q0);
            Bs[q0 + 0][row] = w.x;
            Bs[q0 + 1][row] = w.y;
            Bs[q0 + 2][row] = w.z;
            Bs[q0 + 3][row] = w.w;
        }
        __syncthreads();
        mma_tile(As, Bs, tm, tn, acc);
        __syncthreads();
    }

    const float4 bc0 = *(const float4 *)(bc + bn + tn);
    const float4 bc1 = *(const float4 *)(bc + bn + tn + 4);
#pragma unroll
    for (int i = 0; i < 8; ++i) {
        const int gm = bm + tm + i;
        const size_t base = (size_t)gm * E_DIM + bn + tn;
        const float4 x0 = *(const float4 *)(x + base);
        const float4 x1v = *(const float4 *)(x + base + 4);
        const float2 c0 = unpack2(acc[i][0]);
        const float2 c1 = unpack2(acc[i][1]);
        const float2 c2 = unpack2(acc[i][2]);
        const float2 c3 = unpack2(acc[i][3]);
        float4 o0 = make_float4(c0.x + x0.x + bc0.x, c0.y + x0.y + bc0.y,
                                c1.x + x0.z + bc0.z, c1.y + x0.w + bc0.w);
        float4 o1 = make_float4(c2.x + x1v.x + bc1.x, c2.y + x1v.y + bc1.y,
                                c3.x + x1v.z + bc1.z, c3.y + x1v.w + bc1.w);
        *(float4 *)(g_y1 + base) = o0;
        *(float4 *)(g_y1 + base + 4) = o1;
    }
}

// ================= GEMM2 =================
// A[m,k] = relu(b1[k] + sum_q fq[m,q]*W1[k,q])   (generated in-tile)
// y2[m,n] = x1[m,n] + b2[n] + sum_k A[m,k] * W2[n,k]
__global__ __launch_bounds__(256, 2) void gemm2_kernel(
    const float *__restrict__ W1, const float *__restrict__ b1,
    const float *__restrict__ W2, const float *__restrict__ b2) {
    __shared__ float As[16][132];
    __shared__ float Bs[16][132];
    __shared__ float w1_s[16][8];
    __shared__ float b1_s[16];

    const int bm = blockIdx.x * 128;
    const int bn = blockIdx.y * 128;
    const int t = threadIdx.x;
    const int tm = (t >> 4) * 8;
    const int tn = (t & 15) * 8;
    const int r0 = t >> 2;
    const int q0 = (t & 3) * 4;

    // Per-thread fq row (A-gen row is fixed: m = t>>1, 2 threads/row)
    const int mrow = t >> 1;
    const int kkh = (t & 1) * 8;
    float fqr[8];
    {
        const float4 *fp = (const float4 *)(g_fq + (size_t)(bm + mrow) * NQ);
        const float4 f0 = fp[0];
        const float4 f1 = fp[1];
        fqr[0] = f0.x; fqr[1] = f0.y; fqr[2] = f0.z; fqr[3] = f0.w;
        fqr[4] = f1.x; fqr[5] = f1.y; fqr[6] = f1.z; fqr[7] = f1.w;
    }

    unsigned long long acc[8][4];
#pragma unroll
    for (int i = 0; i < 8; ++i)
#pragma unroll
        for (int j = 0; j < 4; ++j) acc[i][j] = 0ull;

    for (int k0 = 0; k0 < FFN_DIM; k0 += 16) {
        // stage W1/b1 slice + B (W2) tile
        if (t < 128) {
            w1_s[t >> 3][t & 7] = W1[(size_t)(k0 + (t >> 3)) * 8 + (t & 7)];
        } else if (t < 144) {
            b1_s[t - 128] = b1[k0 + (t - 128)];
        }
#pragma unroll
        for (int p = 0; p < 2; ++p) {
            const int row = r0 + p * 64;
            float4 w = *(const float4 *)(W2 + (size_t)(bn + row) * FFN_DIM + k0 + q0);
            Bs[q0 + 0][row] = w.x;
            Bs[q0 + 1][row] = w.y;
            Bs[q0 + 2][row] = w.z;
            Bs[q0 + 3][row] = w.w;
        }
        __syncthreads();
        // generate A tile: h = relu(fq . W1 + b1)
#pragma unroll
        for (int kk = 0; kk < 8; ++kk) {
            float s = b1_s[kkh + kk];
#pragma unroll
            for (int q = 0; q < 8; ++q)
                s = fmaf(fqr[q], w1_s[kkh + kk][q], s);
            As[kkh + kk][mrow] = fmaxf(s, 0.0f);
        }
        __syncthreads();
        mma_tile(As, Bs, tm, tn, acc);
        __syncthreads();
    }

    const float4 b20 = *(const float4 *)(b2 + bn + tn);
    const float4 b21 = *(const float4 *)(b2 + bn + tn + 4);
#pragma unroll
    for (int i = 0; i < 8; ++i) {
        const int gm = bm + tm + i;
        const size_t base = (size_t)gm * E_DIM + bn + tn;
        const float4 x0 = *(const float4 *)(g_x1 + base);
        const float4 x1v = *(const float4 *)(g_x1 + base + 4);
        const float2 c0 = unpack2(acc[i][0]);
        const float2 c1 = unpack2(acc[i][1]);
        const float2 c2 = unpack2(acc[i][2]);
        const float2 c3 = unpack2(acc[i][3]);
        float4 o0 = make_float4(c0.x + x0.x + b20.x, c0.y + x0.y + b20.y,
                                c1.x + x0.z + b20.z, c1.y + x0.w + b20.w);
        float4 o1 = make_float4(c2.x + x1v.x + b21.x, c2.y + x1v.y + b21.y,
                                c3.x + x1v.z + b21.z, c3.y + x1v.w + b21.w);
        *(float4 *)(g_y2 + base) = o0;
        *(float4 *)(g_y2 + base + 4) = o1;
    }
}

// ================= LayerNorm kernels =================
__global__ __launch_bounds__(128) void ln1_kernel(const float *__restrict__ gam,
                                                  const float *__restrict__ bet,
                                                  const float *__restrict__ thF) {
    const int row = blockIdx.x;
    const int t = threadIdx.x;
    const size_t base = (size_t)row * E_DIM;
    const float4 v = ((const float4 *)(g_y1 + base))[t];
    float s = v.x + v.y + v.z + v.w;
    float ss = fmaf(v.x, v.x, fmaf(v.y, v.y, fmaf(v.z, v.z, v.w * v.w)));
#pragma unroll
    for (int o = 16; o > 0; o >>= 1) {
        s += __shfl_down_sync(0xffffffffu, s, o);
        ss += __shfl_down_sync(0xffffffffu, ss, o);
    }
    __shared__ float red[8];
    if ((t & 31) == 0) { red[t >> 5] = s; red[4 + (t >> 5)] = ss; }
    __syncthreads();
    const float st = red[0] + red[1] + red[2] + red[3];
    const float sst = red[4] + red[5] + red[6] + red[7];
    const float mu = st * (1.0f / 512.0f);
    const float var = sst * (1.0f / 512.0f) - mu * mu;
    const float inv = rsqrtf(var + 1e-5f);
    const float4 g4 = ((const float4 *)gam)[t];
    const float4 b4 = ((const float4 *)bet)[t];
    float4 o;
    o.x = (v.x - mu) * inv * g4.x + b4.x;
    o.y = (v.y - mu) * inv * g4.y + b4.y;
    o.z = (v.z - mu) * inv * g4.z + b4.z;
    o.w = (v.w - mu) * inv * g4.w + b4.w;
    ((float4 *)(g_x1 + base))[t] = o;
    if (t < 2) {
        const int n = t * 4;
        float4 c;
        c.x = cosf(o.x + thF[n + 0]);
        c.y = cosf(o.y + thF[n + 1]);
        c.z = cosf(o.z + thF[n + 2]);
        c.w = cosf(o.w + thF[n + 3]);
        ((float4 *)(g_fq + (size_t)row * NQ))[t] = c;
    }
}

__global__ __launch_bounds__(128) void ln2_kernel(const float *__restrict__ gam,
                                                  const float *__restrict__ bet,
                                                  float *__restrict__ out) {
    const int row = blockIdx.x;
    const int t = threadIdx.x;
    const size_t base = (size_t)row * E_DIM;
    const float4 v = ((const float4 *)(g_y2 + base))[t];
    float s = v.x + v.y + v.z + v.w;
    float ss = fmaf(v.x, v.x, fmaf(v.y, v.y, fmaf(v.z, v.z, v.w * v.w)));
#pragma unroll
    for (int o = 16; o > 0; o >>= 1) {
        s += __shfl_down_sync(0xffffffffu, s, o);
        ss += __shfl_down_sync(0xffffffffu, ss, o);
    }
    __shared__ float red[8];
    if ((t & 31) == 0) { red[t >> 5] = s; red[4 + (t >> 5)] = ss; }
    __syncthreads();
    const float st = red[0] + red[1] + red[2] + red[3];
    const float sst = red[4] + red[5] + red[6] + red[7];
    const float mu = st * (1.0f / 512.0f);
    const float var = sst * (1.0f / 512.0f) - mu * mu;
    const float inv = rsqrtf(var + 1e-5f);
    const float4 g4 = ((const float4 *)gam)[t];
    const float4 b4 = ((const float4 *)bet)[t];
    float4 o;
    o.x = (v.x - mu) * inv * g4.x + b4.x;
    o.y = (v.y - mu) * inv * g4.y + b4.y;
    o.z = (v.z - mu) * inv * g4.z + b4.z;
    o.w = (v.w - mu) * inv * g4.w + b4.w;
    ((float4 *)(out + base))[t] = o;
}

// ================= launch =================
extern "C" void kernel_launch(void *const *d_in, const int *in_sizes, int n_in,
                              void *d_out, int out_size) {
    const float *x   = (const float *)d_in[0];
    const float *thA = (const float *)d_in[1];   // [64,8] -> flat [512]
    const float *Wc  = (const float *)d_in[2];   // [512,512]
    const float *bc  = (const float *)d_in[3];
    const float *g1  = (const float *)d_in[4];
    const float *be1 = (const float *)d_in[5];
    const float *thF = (const float *)d_in[6];   // [8]
    const float *W1  = (const float *)d_in[7];   // [2048,8]
    const float *b1  = (const float *)d_in[8];
    const float *W2  = (const float *)d_in[9];   // [512,2048]
    const float *b2  = (const float *)d_in[10];
    const float *g2  = (const float *)d_in[11];
    const float *be2 = (const float *)d_in[12];
    float *out = (float *)d_out;

    dim3 gemm_grid(M_TOTAL / 128, E_DIM / 128);  // (256, 4)
    gemm1_kernel<<<gemm_grid, 256>>>(x, thA, Wc, bc);
    ln1_kernel<<<M_TOTAL, 128>>>(g1, be1, thF);
    gemm2_kernel<<<gemm_grid, 256>>>(W1, b1, W2, b2);
    ln2_kernel<<<M_TOTAL, 128>>>(g2, be2, out);
}

// round 4
// speedup vs baseline: 4.0442x; 4.0442x over previous
#include <cuda_runtime.h>
#include <cstdint>

#define M_TOTAL 32768
#define E_DIM   512
#define FFN_DIM 2048

// Feature gate: tcgen05 only exists on the sm_103a ("arch-accelerated") target.
// Non-"a" PTX stages (compute_103 / sm_103) compile the FMA fallback instead.
#if defined(__CUDA_ARCH__) && defined(__CUDA_ARCH_FEAT_SM103_ALL)
#define HAS_TCGEN05 1
#else
#define HAS_TCGEN05 0
#endif

// scratch (device globals, allocation-free)
__device__ float g_y1[(size_t)M_TOTAL * E_DIM];   // raw attn matmul out
__device__ float g_x1[(size_t)M_TOTAL * E_DIM];   // LN1 out
__device__ float g_y2[(size_t)M_TOTAL * E_DIM];   // raw ffn matmul out
__device__ float g_fq[(size_t)M_TOTAL * 8];       // cos(x1[:, :8] + theta_ffn)

// ---------------- smem layout (dynamic) ----------------
#define SM_TMEM  0
#define SM_MBAR  16          // two 8B mbarriers at 16, 24
#define SM_AUX   64          // theta (2KB) or fq (4KB)
#define SM_A0    8192        // 16KB A tile buf0
#define SM_A1    24576       // 16KB A tile buf1
#define SM_B0    40960       // 64KB B tile buf0
#define SM_B1    106496      // 64KB B tile buf1
#define SMEM_BYTES 172032
#define SM_EP    8192        // epilogue bounce (reuses A/B area)

// idesc: dtype=F32(1<<4), atype=TF32(2<<7), btype=TF32(2<<10), N=128(16<<17), M=128(8<<24)
#define IDESC_TF32 ((1u<<4)|(2u<<7)|(2u<<10)|(16u<<17)|(8u<<24))

// ---------------- common helpers ----------------
__device__ __forceinline__ uint32_t smem_u32(const void* p) {
    uint32_t a;
    asm("{ .reg .u64 t; cvta.to.shared.u64 t, %1; cvt.u32.u64 %0, t; }" : "=r"(a) : "l"(p));
    return a;
}
__device__ __forceinline__ void fma2(unsigned long long &d,
                                     unsigned long long a,
                                     unsigned long long b) {
    asm("fma.rn.f32x2 %0, %1, %2, %0;" : "+l"(d) : "l"(a), "l"(b));
}
__device__ __forceinline__ unsigned long long pack2(float x) {
    unsigned long long r;
    asm("mov.b64 %0, {%1, %1};" : "=l"(r) : "f"(x));
    return r;
}
__device__ __forceinline__ float2 unpack2(unsigned long long v) {
    float2 r;
    asm("mov.b64 {%0, %1}, %2;" : "=f"(r.x), "=f"(r.y) : "l"(v));
    return r;
}

#if HAS_TCGEN05
// ---------------- tcgen05 helpers (sm_103a only) ----------------
__device__ __forceinline__ uint32_t elect_one() {
    uint32_t p;
    asm volatile("{ .reg .pred p; elect.sync _|p, 0xFFFFFFFF; selp.b32 %0, 1, 0, p; }" : "=r"(p));
    return p;
}
__device__ __forceinline__ uint32_t f2tf32(float f) {
    uint32_t r;
    asm("cvt.rna.tf32.f32 %0, %1;" : "=r"(r) : "f"(f));
    return r;
}
__device__ __forceinline__ uint64_t make_desc(uint32_t addr) {
    // SW128 K-major: layout=2, version=1, SBO=64 (1024B = 8 rows), LBO=1 (16B)
    return (uint64_t(2) << 61) | (uint64_t(1) << 46) | (uint64_t(64) << 32) |
           (uint64_t(1) << 16) | ((addr >> 4) & 0x3FFFu);
}
__device__ __forceinline__ void mma_tf32(uint32_t d, uint64_t ad, uint64_t bd,
                                         uint32_t idesc, uint32_t en) {
    asm volatile(
        "{\n\t.reg .pred p;\n\tsetp.ne.u32 p, %5, 0;\n\t"
        "tcgen05.mma.cta_group::1.kind::tf32 [%0], %1, %2, %3, {%4, %4, %4, %4}, p;\n\t}"
        :: "r"(d), "l"(ad), "l"(bd), "r"(idesc), "r"(0u), "r"(en) : "memory");
}
__device__ __forceinline__ void tc_commit(uint32_t mbar) {
    asm volatile(
        "tcgen05.commit.cta_group::1.mbarrier::arrive::one.shared::cluster.b64 [%0];"
        :: "r"(mbar) : "memory");
}
__device__ __forceinline__ void mbar_init(uint32_t mbar, uint32_t cnt) {
    asm volatile("mbarrier.init.shared.b64 [%0], %1;" :: "r"(mbar), "r"(cnt) : "memory");
}
__device__ __forceinline__ void mbar_wait(uint32_t mbar, uint32_t ph) {
    asm volatile(
        "{\n\t.reg .pred P1;\n\t"
        "W_%=:\n\t"
        "mbarrier.try_wait.parity.acquire.cta.shared::cta.b64 P1, [%0], %1, 0x989680;\n\t"
        "@P1 bra D_%=;\n\t"
        "bra W_%=;\n\t"
        "D_%=:\n\t}"
        :: "r"(mbar), "r"(ph) : "memory");
}
__device__ __forceinline__ void fence_proxy_async_cta() {
    asm volatile("fence.proxy.async.shared::cta;" ::: "memory");
}
__device__ __forceinline__ void tc_fence_after() {
    asm volatile("tcgen05.fence::after_thread_sync;" ::: "memory");
}
#define TC_ALLOC(dst, n)   asm volatile("tcgen05.alloc.cta_group::1.sync.aligned.shared::cta.b32 [%0], %1;" :: "r"(dst), "r"(n) : "memory")
#define TC_RELINQ()        asm volatile("tcgen05.relinquish_alloc_permit.cta_group::1.sync.aligned;")
#define TC_DEALLOC(t, n)   asm volatile("tcgen05.dealloc.cta_group::1.sync.aligned.b32 %0, %1;" :: "r"(t), "r"(n))
#define TC_WAIT_LD()       asm volatile("tcgen05.wait::ld.sync.aligned;" ::: "memory")
#define LDTM_X32(r, a) \
    asm volatile("tcgen05.ld.sync.aligned.32x32b.x32.b32 " \
        "{%0,%1,%2,%3,%4,%5,%6,%7,%8,%9,%10,%11,%12,%13,%14,%15," \
        "%16,%17,%18,%19,%20,%21,%22,%23,%24,%25,%26,%27,%28,%29,%30,%31}, [%32];" \
        : "=r"((r)[0]),"=r"((r)[1]),"=r"((r)[2]),"=r"((r)[3]),"=r"((r)[4]),"=r"((r)[5]),"=r"((r)[6]),"=r"((r)[7]), \
          "=r"((r)[8]),"=r"((r)[9]),"=r"((r)[10]),"=r"((r)[11]),"=r"((r)[12]),"=r"((r)[13]),"=r"((r)[14]),"=r"((r)[15]), \
          "=r"((r)[16]),"=r"((r)[17]),"=r"((r)[18]),"=r"((r)[19]),"=r"((r)[20]),"=r"((r)[21]),"=r"((r)[22]),"=r"((r)[23]), \
          "=r"((r)[24]),"=r"((r)[25]),"=r"((r)[26]),"=r"((r)[27]),"=r"((r)[28]),"=r"((r)[29]),"=r"((r)[30]),"=r"((r)[31]) \
        : "r"(a))

// swizzled 16B-block column within a 128B row
__device__ __forceinline__ uint32_t swz_off(int row, int q16) {
    return (uint32_t)(row * 128 + ((q16 ^ (row & 7)) * 16));
}

// MMA issue for one 128x512x32 tile (4 ksteps x 4 nchunks)
__device__ __forceinline__ void issue_tile(uint32_t sb, uint32_t a_off, uint32_t b_off,
                                           uint32_t tmem, bool first, uint32_t mbar) {
    const uint64_t ab = make_desc(sb + a_off);
    const uint64_t bb = make_desc(sb + b_off);
    if (elect_one()) {
#pragma unroll
        for (int ks = 0; ks < 4; ++ks) {
            const uint32_t en = (!first || ks > 0) ? 1u : 0u;
#pragma unroll
            for (int nc = 0; nc < 4; ++nc)
                mma_tf32(tmem + nc * 128, ab + ks * 2, bb + nc * 1024 + ks * 2,
                         IDESC_TF32, en);
        }
        tc_commit(mbar);
    }
}

// epilogue: TMEM D[128x512] -> dst rows [bm..bm+128), coalesced via smem bounce
__device__ __forceinline__ void epilogue_store(char* sm, uint32_t tmem,
                                               float* dst, int bm, int t) {
    const int w = t >> 5, lane = t & 31;
    const int sp = w & 3, half = w >> 2;
    float* eb = (float*)(sm + SM_EP + w * 4608);  // [32][36]
    const int rbase = sp * 32;
#pragma unroll 1
    for (int ch = 0; ch < 8; ++ch) {
        const int colb = half * 256 + ch * 32;
        uint32_t r[32];
        LDTM_X32(r, tmem + colb);
        TC_WAIT_LD();
#pragma unroll
        for (int c4 = 0; c4 < 8; ++c4) {
            float4 v = make_float4(__uint_as_float(r[c4 * 4 + 0]),
                                   __uint_as_float(r[c4 * 4 + 1]),
                                   __uint_as_float(r[c4 * 4 + 2]),
                                   __uint_as_float(r[c4 * 4 + 3]));
            *(float4*)(eb + lane * 36 + c4 * 4) = v;
        }
        __syncwarp();
#pragma unroll
        for (int j = 0; j < 32; ++j)
            dst[(size_t)(bm + rbase + j) * E_DIM + colb + lane] = eb[j * 36 + lane];
        __syncwarp();
    }
}
#endif  // HAS_TCGEN05

// ---------------- FMA fallback micro-kernel ----------------
__device__ __forceinline__ void mma_tile_fb(const float (*As)[132], const float (*Bs)[132],
                                            int tm, int tn,
                                            unsigned long long (&acc)[8][4]) {
#pragma unroll
    for (int k = 0; k < 16; ++k) {
        const float4 a0 = *(const float4 *)&As[k][tm];
        const float4 a1 = *(const float4 *)&As[k][tm + 4];
        const ulonglong2 bb0 = *(const ulonglong2 *)&Bs[k][tn];
        const ulonglong2 bb1 = *(const ulonglong2 *)&Bs[k][tn + 4];
        unsigned long long av[8];
        av[0] = pack2(a0.x); av[1] = pack2(a0.y);
        av[2] = pack2(a0.z); av[3] = pack2(a0.w);
        av[4] = pack2(a1.x); av[5] = pack2(a1.y);
        av[6] = pack2(a1.z); av[7] = pack2(a1.w);
        unsigned long long bv[4] = {bb0.x, bb0.y, bb1.x, bb1.y};
#pragma unroll
        for (int i = 0; i < 8; ++i)
#pragma unroll
            for (int j = 0; j < 4; ++j)
                fma2(acc[i][j], av[i], bv[j]);
    }
}

// ================= GEMM1 =================
// g_y1[m,n] = sum_e cos(x[m,e]+theta[e]) * Wc[n,e]
__global__ __launch_bounds__(256, 1)
void gemm1_tc(const float* __restrict__ x, const float* __restrict__ theta,
              const float* __restrict__ Wc) {
    extern __shared__ char sm[];
    const int t = threadIdx.x;
    const int bm = blockIdx.x * 128;
#if HAS_TCGEN05
    const uint32_t sb = smem_u32(sm);
    if (t < 32) TC_ALLOC(sb + SM_TMEM, 512);
    if (t == 0) { mbar_init(sb + SM_MBAR, 1); mbar_init(sb + SM_MBAR + 8, 1); }
    ((float*)(sm + SM_AUX))[t] = theta[t];
    ((float*)(sm + SM_AUX))[t + 256] = theta[t + 256];
    __syncthreads();
    uint32_t tmem;
    asm volatile("ld.shared.b32 %0, [%1];" : "=r"(tmem) : "r"(sb + SM_TMEM));

    const float* th_s = (const float*)(sm + SM_AUX);
    const int NIT = E_DIM / 32;  // 16

    auto load_tiles = [&](int it, uint32_t Aoff, uint32_t Boff) {
        const int k0 = it * 32;
#pragma unroll
        for (int j = 0; j < 4; ++j) {
            const int idx = t + j * 256;
            const int row = idx >> 3, q4 = idx & 7;
            const float4 v = *(const float4*)(x + (size_t)(bm + row) * E_DIM + k0 + q4 * 4);
            const float4 thv = *(const float4*)(th_s + k0 + q4 * 4);
            uint4 o;
            o.x = f2tf32(cosf(v.x + thv.x));
            o.y = f2tf32(cosf(v.y + thv.y));
            o.z = f2tf32(cosf(v.z + thv.z));
            o.w = f2tf32(cosf(v.w + thv.w));
            *(uint4*)(sm + Aoff + swz_off(row, q4)) = o;
        }
#pragma unroll
        for (int j = 0; j < 16; ++j) {
            const int idx = t + j * 256;
            const int row = idx >> 3, q4 = idx & 7;
            const float4 w = *(const float4*)(Wc + (size_t)row * E_DIM + k0 + q4 * 4);
            uint4 o;
            o.x = f2tf32(w.x); o.y = f2tf32(w.y); o.z = f2tf32(w.z); o.w = f2tf32(w.w);
            *(uint4*)(sm + Boff + swz_off(row, q4)) = o;
        }
        fence_proxy_async_cta();
    };

    load_tiles(0, SM_A0, SM_B0);
    __syncthreads();

    int ph[2] = {0, 0};
    for (int it = 0; it < NIT; ++it) {
        const int buf = it & 1, ob = buf ^ 1;
        if (t < 32)
            issue_tile(sb, buf ? SM_A1 : SM_A0, buf ? SM_B1 : SM_B0, tmem, it == 0,
                       sb + SM_MBAR + buf * 8);
        if (it + 1 < NIT) {
            if (it >= 1) { mbar_wait(sb + SM_MBAR + ob * 8, ph[ob]); ph[ob] ^= 1; }
            load_tiles(it + 1, ob ? SM_A1 : SM_A0, ob ? SM_B1 : SM_B0);
        }
        __syncthreads();
    }
    const int lb = (NIT - 1) & 1;
    mbar_wait(sb + SM_MBAR + lb * 8, ph[lb]);
    tc_fence_after();
    __syncthreads();

    epilogue_store(sm, tmem, g_y1, bm, t);

    __syncthreads();
    if (t < 32) { TC_RELINQ(); TC_DEALLOC(tmem, 512); }
#else
    // -------- FMA fallback --------
    float (*As)[132] = (float(*)[132])sm;
    float (*Bs)[132] = (float(*)[132])(sm + 8448);
    const int tm = (t >> 4) * 8;
    const int tn = (t & 15) * 8;
    const int r0 = t >> 2;
    const int q0 = (t & 3) * 4;
#pragma unroll 1
    for (int bn = 0; bn < E_DIM; bn += 128) {
        unsigned long long acc[8][4];
#pragma unroll
        for (int i = 0; i < 8; ++i)
#pragma unroll
            for (int j = 0; j < 4; ++j) acc[i][j] = 0ull;
#pragma unroll 1
        for (int k0 = 0; k0 < E_DIM; k0 += 16) {
#pragma unroll
            for (int p = 0; p < 2; ++p) {
                const int row = r0 + p * 64;
                float4 v = *(const float4 *)(x + (size_t)(bm + row) * E_DIM + k0 + q0);
                As[q0 + 0][row] = cosf(v.x + theta[k0 + q0 + 0]);
                As[q0 + 1][row] = cosf(v.y + theta[k0 + q0 + 1]);
                As[q0 + 2][row] = cosf(v.z + theta[k0 + q0 + 2]);
                As[q0 + 3][row] = cosf(v.w + theta[k0 + q0 + 3]);
                float4 w = *(const float4 *)(Wc + (size_t)(bn + row) * E_DIM + k0 + q0);
                Bs[q0 + 0][row] = w.x;
                Bs[q0 + 1][row] = w.y;
                Bs[q0 + 2][row] = w.z;
                Bs[q0 + 3][row] = w.w;
            }
            __syncthreads();
            mma_tile_fb(As, Bs, tm, tn, acc);
            __syncthreads();
        }
#pragma unroll
        for (int i = 0; i < 8; ++i) {
            const size_t base = (size_t)(bm + tm + i) * E_DIM + bn + tn;
            const float2 c0 = unpack2(acc[i][0]);
            const float2 c1 = unpack2(acc[i][1]);
            const float2 c2 = unpack2(acc[i][2]);
            const float2 c3 = unpack2(acc[i][3]);
            *(float4 *)(g_y1 + base) = make_float4(c0.x, c0.y, c1.x, c1.y);
            *(float4 *)(g_y1 + base + 4) = make_float4(c2.x, c2.y, c3.x, c3.y);
        }
    }
#endif
}

// ================= GEMM2 =================
// A[m,k] = relu(b1[k] + sum_q fq[m,q]*W1[k,q]) generated on the fly
// g_y2[m,n] = sum_k A[m,k] * W2[n,k]
__global__ __launch_bounds__(256, 1)
void gemm2_tc(const float* __restrict__ W1, const float* __restrict__ b1,
              const float* __restrict__ W2) {
    extern __shared__ char sm[];
    const int t = threadIdx.x;
    const int bm = blockIdx.x * 128;
#if HAS_TCGEN05
    const uint32_t sb = smem_u32(sm);
    if (t < 32) TC_ALLOC(sb + SM_TMEM, 512);
    if (t == 0) { mbar_init(sb + SM_MBAR, 1); mbar_init(sb + SM_MBAR + 8, 1); }
    *(float4*)(sm + SM_AUX + t * 16) = *(const float4*)(g_fq + (size_t)bm * 8 + t * 4);
    __syncthreads();
    uint32_t tmem;
    asm volatile("ld.shared.b32 %0, [%1];" : "=r"(tmem) : "r"(sb + SM_TMEM));

    const int NIT = FFN_DIM / 32;  // 64
    const int kl = t & 31;
    const int rb = (t >> 5) * 16;

    auto load_tiles = [&](int it, uint32_t Aoff, uint32_t Boff) {
        const int k0 = it * 32;
        const float4 w1a = *(const float4*)(W1 + (size_t)(k0 + kl) * 8);
        const float4 w1b = *(const float4*)(W1 + (size_t)(k0 + kl) * 8 + 4);
        const float b1v = b1[k0 + kl];
#pragma unroll
        for (int i = 0; i < 16; ++i) {
            const int r = rb + i;
            const float4 f0 = *(const float4*)(sm + SM_AUX + r * 32);
            const float4 f1 = *(const float4*)(sm + SM_AUX + r * 32 + 16);
            float h = b1v;
            h = fmaf(f0.x, w1a.x, h); h = fmaf(f0.y, w1a.y, h);
            h = fmaf(f0.z, w1a.z, h); h = fmaf(f0.w, w1a.w, h);
            h = fmaf(f1.x, w1b.x, h); h = fmaf(f1.y, w1b.y, h);
            h = fmaf(f1.z, w1b.z, h); h = fmaf(f1.w, w1b.w, h);
            h = fmaxf(h, 0.0f);
            *(uint32_t*)(sm + Aoff + (uint32_t)(r * 128 + (((kl >> 2) ^ (r & 7)) * 16 + (kl & 3) * 4))) = f2tf32(h);
        }
#pragma unroll
        for (int j = 0; j < 16; ++j) {
            const int idx = t + j * 256;
            const int row = idx >> 3, q4 = idx & 7;
            const float4 w = *(const float4*)(W2 + (size_t)row * FFN_DIM + k0 + q4 * 4);
            uint4 o;
            o.x = f2tf32(w.x); o.y = f2tf32(w.y); o.z = f2tf32(w.z); o.w = f2tf32(w.w);
            *(uint4*)(sm + Boff + swz_off(row, q4)) = o;
        }
        fence_proxy_async_cta();
    };

    load_tiles(0, SM_A0, SM_B0);
    __syncthreads();

    int ph[2] = {0, 0};
    for (int it = 0; it < NIT; ++it) {
        const int buf = it & 1, ob = buf ^ 1;
        if (t < 32)
            issue_tile(sb, buf ? SM_A1 : SM_A0, buf ? SM_B1 : SM_B0, tmem, it == 0,
                       sb + SM_MBAR + buf * 8);
        if (it + 1 < NIT) {
            if (it >= 1) { mbar_wait(sb + SM_MBAR + ob * 8, ph[ob]); ph[ob] ^= 1; }
            load_tiles(it + 1, ob ? SM_A1 : SM_A0, ob ? SM_B1 : SM_B0);
        }
        __syncthreads();
    }
    const int lb = (NIT - 1) & 1;
    mbar_wait(sb + SM_MBAR + lb * 8, ph[lb]);
    tc_fence_after();
    __syncthreads();

    epilogue_store(sm, tmem, g_y2, bm, t);

    __syncthreads();
    if (t < 32) { TC_RELINQ(); TC_DEALLOC(tmem, 512); }
#else
    // -------- FMA fallback --------
    float (*As)[132] = (float(*)[132])sm;
    float (*Bs)[132] = (float(*)[132])(sm + 8448);
    float* fqs = (float*)(sm + 17408);
    const int tm = (t >> 4) * 8;
    const int tn = (t & 15) * 8;
    const int r0 = t >> 2;
    const int q0 = (t & 3) * 4;
    const int mrow = t >> 1;
    const int kkh = (t & 1) * 8;

    *(float4*)(fqs + t * 4) = *(const float4*)(g_fq + (size_t)bm * 8 + t * 4);
    __syncthreads();
    float fqr[8];
    {
        const float4 f0 = *(const float4*)(fqs + mrow * 8);
        const float4 f1 = *(const float4*)(fqs + mrow * 8 + 4);
        fqr[0] = f0.x; fqr[1] = f0.y; fqr[2] = f0.z; fqr[3] = f0.w;
        fqr[4] = f1.x; fqr[5] = f1.y; fqr[6] = f1.z; fqr[7] = f1.w;
    }

#pragma unroll 1
    for (int bn = 0; bn < E_DIM; bn += 128) {
        unsigned long long acc[8][4];
#pragma unroll
        for (int i = 0; i < 8; ++i)
#pragma unroll
            for (int j = 0; j < 4; ++j) acc[i][j] = 0ull;
#pragma unroll 1
        for (int k0 = 0; k0 < FFN_DIM; k0 += 16) {
#pragma unroll
            for (int kk = 0; kk < 8; ++kk) {
                const int kg = k0 + kkh + kk;
                float s = b1[kg];
#pragma unroll
                for (int q = 0; q < 8; ++q)
                    s = fmaf(fqr[q], W1[(size_t)kg * 8 + q], s);
                As[kkh + kk][mrow] = fmaxf(s, 0.0f);
            }
#pragma unroll
            for (int p = 0; p < 2; ++p) {
                const int row = r0 + p * 64;
                float4 w = *(const float4 *)(W2 + (size_t)(bn + row) * FFN_DIM + k0 + q0);
                Bs[q0 + 0][row] = w.x;
                Bs[q0 + 1][row] = w.y;
                Bs[q0 + 2][row] = w.z;
                Bs[q0 + 3][row] = w.w;
            }
            __syncthreads();
            mma_tile_fb(As, Bs, tm, tn, acc);
            __syncthreads();
        }
#pragma unroll
        for (int i = 0; i < 8; ++i) {
            const size_t base = (size_t)(bm + tm + i) * E_DIM + bn + tn;
            const float2 c0 = unpack2(acc[i][0]);
            const float2 c1 = unpack2(acc[i][1]);
            const float2 c2 = unpack2(acc[i][2]);
            const float2 c3 = unpack2(acc[i][3]);
            *(float4 *)(g_y2 + base) = make_float4(c0.x, c0.y, c1.x, c1.y);
            *(float4 *)(g_y2 + base + 4) = make_float4(c2.x, c2.y, c3.x, c3.y);
        }
    }
#endif
}

// ================= LayerNorm kernels =================
__global__ __launch_bounds__(128) void ln1_kernel(
    const float* __restrict__ x, const float* __restrict__ bc,
    const float* __restrict__ gam, const float* __restrict__ bet,
    const float* __restrict__ thF) {
    const int row = blockIdx.x;
    const int t = threadIdx.x;
    const size_t base = (size_t)row * E_DIM;
    const float4 vy = ((const float4*)(g_y1 + base))[t];
    const float4 vx = ((const float4*)(x + base))[t];
    const float4 vb = ((const float4*)bc)[t];
    float4 v = make_float4(vy.x + vx.x + vb.x, vy.y + vx.y + vb.y,
                           vy.z + vx.z + vb.z, vy.w + vx.w + vb.w);
    float s = v.x + v.y + v.z + v.w;
    float ss = fmaf(v.x, v.x, fmaf(v.y, v.y, fmaf(v.z, v.z, v.w * v.w)));
#pragma unroll
    for (int o = 16; o > 0; o >>= 1) {
        s += __shfl_down_sync(0xffffffffu, s, o);
        ss += __shfl_down_sync(0xffffffffu, ss, o);
    }
    __shared__ float red[8];
    if ((t & 31) == 0) { red[t >> 5] = s; red[4 + (t >> 5)] = ss; }
    __syncthreads();
    const float st = red[0] + red[1] + red[2] + red[3];
    const float sst = red[4] + red[5] + red[6] + red[7];
    const float mu = st * (1.0f / 512.0f);
    const float var = sst * (1.0f / 512.0f) - mu * mu;
    const float inv = rsqrtf(var + 1e-5f);
    const float4 g4 = ((const float4*)gam)[t];
    const float4 b4 = ((const float4*)bet)[t];
    float4 o;
    o.x = (v.x - mu) * inv * g4.x + b4.x;
    o.y = (v.y - mu) * inv * g4.y + b4.y;
    o.z = (v.z - mu) * inv * g4.z + b4.z;
    o.w = (v.w - mu) * inv * g4.w + b4.w;
    ((float4*)(g_x1 + base))[t] = o;
    if (t < 2) {
        const int n = t * 4;
        float4 c;
        c.x = cosf(o.x + thF[n + 0]);
        c.y = cosf(o.y + thF[n + 1]);
        c.z = cosf(o.z + thF[n + 2]);
        c.w = cosf(o.w + thF[n + 3]);
        ((float4*)(g_fq + (size_t)row * 8))[t] = c;
    }
}

__global__ __launch_bounds__(128) void ln2_kernel(
    const float* __restrict__ b2, const float* __restrict__ gam,
    const float* __restrict__ bet, float* __restrict__ out) {
    const int row = blockIdx.x;
    const int t = threadIdx.x;
    const size_t base = (size_t)row * E_DIM;
    const float4 vy = ((const float4*)(g_y2 + base))[t];
    const float4 vx = ((const float4*)(g_x1 + base))[t];
    const float4 vb = ((const float4*)b2)[t];
    float4 v = make_float4(vy.x + vx.x + vb.x, vy.y + vx.y + vb.y,
                           vy.z + vx.z + vb.z, vy.w + vx.w + vb.w);
    float s = v.x + v.y + v.z + v.w;
    float ss = fmaf(v.x, v.x, fmaf(v.y, v.y, fmaf(v.z, v.z, v.w * v.w)));
#pragma unroll
    for (int o = 16; o > 0; o >>= 1) {
        s += __shfl_down_sync(0xffffffffu, s, o);
        ss += __shfl_down_sync(0xffffffffu, ss, o);
    }
    __shared__ float red[8];
    if ((t & 31) == 0) { red[t >> 5] = s; red[4 + (t >> 5)] = ss; }
    __syncthreads();
    const float st = red[0] + red[1] + red[2] + red[3];
    const float sst = red[4] + red[5] + red[6] + red[7];
    const float mu = st * (1.0f / 512.0f);
    const float var = sst * (1.0f / 512.0f) - mu * mu;
    const float inv = rsqrtf(var + 1e-5f);
    const float4 g4 = ((const float4*)gam)[t];
    const float4 b4 = ((const float4*)bet)[t];
    float4 o;
    o.x = (v.x - mu) * inv * g4.x + b4.x;
    o.y = (v.y - mu) * inv * g4.y + b4.y;
    o.z = (v.z - mu) * inv * g4.z + b4.z;
    o.w = (v.w - mu) * inv * g4.w + b4.w;
    ((float4*)(out + base))[t] = o;
}

// ================= launch =================
extern "C" void kernel_launch(void* const* d_in, const int* in_sizes, int n_in,
                              void* d_out, int out_size) {
    const float* x   = (const float*)d_in[0];
    const float* thA = (const float*)d_in[1];
    const float* Wc  = (const float*)d_in[2];
    const float* bc  = (const float*)d_in[3];
    const float* g1  = (const float*)d_in[4];
    const float* be1 = (const float*)d_in[5];
    const float* thF = (const float*)d_in[6];
    const float* W1  = (const float*)d_in[7];
    const float* b1  = (const float*)d_in[8];
    const float* W2  = (const float*)d_in[9];
    const float* b2  = (const float*)d_in[10];
    const float* g2  = (const float*)d_in[11];
    const float* be2 = (const float*)d_in[12];
    float* out = (float*)d_out;

    cudaFuncSetAttribute(gemm1_tc, cudaFuncAttributeMaxDynamicSharedMemorySize, SMEM_BYTES);
    cudaFuncSetAttribute(gemm2_tc, cudaFuncAttributeMaxDynamicSharedMemorySize, SMEM_BYTES);

    gemm1_tc<<<M_TOTAL / 128, 256, SMEM_BYTES>>>(x, thA, Wc);
    ln1_kernel<<<M_TOTAL, 128>>>(x, bc, g1, be1, thF);
    gemm2_tc<<<M_TOTAL / 128, 256, SMEM_BYTES>>>(W1, b1, W2);
    ln2_kernel<<<M_TOTAL, 128>>>(b2, g2, be2, out);
}

// round 7
// speedup vs baseline: 4.2963x; 1.0624x over previous
#include <cuda_runtime.h>
#include <cstdint>

#define M_TOTAL 32768
#define E_DIM   512
#define FFN_DIM 2048

#if defined(__CUDA_ARCH__) && defined(__CUDA_ARCH_FEAT_SM103_ALL)
#define HAS_TCGEN05 1
#else
#define HAS_TCGEN05 0
#endif

// scratch (device globals, allocation-free)
__device__ float g_x1[(size_t)M_TOTAL * E_DIM];   // LN1 out
__device__ float g_fq[(size_t)M_TOTAL * 8];       // cos(x1[:, :8] + theta_ffn)
// packed weights: tf32, SW128 smem image, 64KB per 512x32 k-tile
__device__ uint4 g_Wcp[65536];                    // Wc: 16 tiles x 64KB = 1MB
__device__ uint4 g_W2p[262144];                   // W2: 64 tiles x 64KB = 4MB

// ---------------- smem layout (dynamic) ----------------
#define SM_TMEM  0
#define MB_MMA0  16
#define MB_MMA1  24
#define SM_RED   64          // 512 floats: s[128][2], ss[128][2]
#define SM_PAR   2112        // 3 x 512 floats (bias, gamma, beta)
#define SM_TH    8256        // gemm1: theta 512 floats / gemm2: fq 4KB
#define SM_A0    16384       // 16KB
#define SM_A1    32768       // 16KB
#define SM_B0    49152       // 64KB
#define SM_B1    114688      // 64KB
#define SMEM_BYTES 180224
#define SM_EP    16384       // epilogue bounce (reuses A/B space post-mainloop)

// idesc: dtype=F32(1<<4), atype=TF32(2<<7), btype=TF32(2<<10), N=128(16<<17), M=128(8<<24)
#define IDESC_TF32 ((1u<<4)|(2u<<7)|(2u<<10)|(16u<<17)|(8u<<24))

// ---------------- common helpers (all PTX stages) ----------------
__device__ __forceinline__ uint32_t smem_u32(const void* p) {
    uint32_t a;
    asm("{ .reg .u64 t; cvta.to.shared.u64 t, %1; cvt.u32.u64 %0, t; }" : "=r"(a) : "l"(p));
    return a;
}
__device__ __forceinline__ uint32_t f2tf32(float f) {
    uint32_t r;
    asm("cvt.rna.tf32.f32 %0, %1;" : "=r"(r) : "f"(f));
    return r;
}
// swizzled byte offset of 16B group q16 within row (128B rows, SW128)
__device__ __forceinline__ uint32_t swz_off(int row, int q16) {
    return (uint32_t)(row * 128 + ((q16 ^ (row & 7)) * 16));
}

// ================= weight repack =================
// src [512][K] fp32 -> tiles of 64KB: tile t holds cols t*32..t*32+31 of all 512
// rows, tf32-rounded, laid out exactly as the SW128 smem image.
__global__ __launch_bounds__(256) void repack_kernel(const float* __restrict__ src,
                                                     int K, int which) {
    uint4* dst = which ? g_W2p : g_Wcp;
    const int g = blockIdx.x * blockDim.x + threadIdx.x;   // one 16B group
    const int total = 512 * K / 4;
    if (g >= total) return;
    const int q16 = g & 7;
    const int row = (g >> 3) & 511;
    const int tile = g >> 12;
    const float4 v = *(const float4*)(src + (size_t)row * K + tile * 32 + q16 * 4);
    uint4 o;
    o.x = f2tf32(v.x); o.y = f2tf32(v.y); o.z = f2tf32(v.z); o.w = f2tf32(v.w);
    *(uint4*)((char*)dst + (size_t)tile * 65536 + swz_off(row, q16)) = o;
}

#if HAS_TCGEN05
// ---------------- tcgen05 helpers (sm_103a only) ----------------
__device__ __forceinline__ uint32_t elect_one() {
    uint32_t p;
    asm volatile("{ .reg .pred p; elect.sync _|p, 0xFFFFFFFF; selp.b32 %0, 1, 0, p; }" : "=r"(p));
    return p;
}
__device__ __forceinline__ uint64_t make_desc(uint32_t addr) {
    return (uint64_t(2) << 61) | (uint64_t(1) << 46) | (uint64_t(64) << 32) |
           (uint64_t(1) << 16) | ((addr >> 4) & 0x3FFFu);
}
__device__ __forceinline__ void mma_tf32(uint32_t d, uint64_t ad, uint64_t bd,
                                         uint32_t idesc, uint32_t en) {
    asm volatile(
        "{\n\t.reg .pred p;\n\tsetp.ne.u32 p, %5, 0;\n\t"
        "tcgen05.mma.cta_group::1.kind::tf32 [%0], %1, %2, %3, {%4, %4, %4, %4}, p;\n\t}"
        :: "r"(d), "l"(ad), "l"(bd), "r"(idesc), "r"(0u), "r"(en) : "memory");
}
__device__ __forceinline__ void tc_commit(uint32_t mbar) {
    asm volatile(
        "tcgen05.commit.cta_group::1.mbarrier::arrive::one.shared::cluster.b64 [%0];"
        :: "r"(mbar) : "memory");
}
__device__ __forceinline__ void mbar_init(uint32_t mbar, uint32_t cnt) {
    asm volatile("mbarrier.init.shared.b64 [%0], %1;" :: "r"(mbar), "r"(cnt) : "memory");
}
__device__ __forceinline__ void mbar_wait(uint32_t mbar, uint32_t ph) {
    asm volatile(
        "{\n\t.reg .pred P1;\n\t"
        "W_%=:\n\t"
        "mbarrier.try_wait.parity.acquire.cta.shared::cta.b64 P1, [%0], %1, 0x989680;\n\t"
        "@P1 bra D_%=;\n\t"
        "bra W_%=;\n\t"
        "D_%=:\n\t}"
        :: "r"(mbar), "r"(ph) : "memory");
}
__device__ __forceinline__ void fence_proxy_async_cta() {
    asm volatile("fence.proxy.async.shared::cta;" ::: "memory");
}
__device__ __forceinline__ void tc_fence_after() {
    asm volatile("tcgen05.fence::after_thread_sync;" ::: "memory");
}
// cp.async (LDGSTS) 16B copy + group fences
__device__ __forceinline__ void cp16(uint32_t dst, const void* src) {
    asm volatile("cp.async.cg.shared.global [%0], [%1], 16;" :: "r"(dst), "l"(src) : "memory");
}
#define CP_COMMIT() asm volatile("cp.async.commit_group;" ::: "memory")
#define CP_WAIT(n)  asm volatile("cp.async.wait_group %0;" :: "n"(n) : "memory")

#define TC_ALLOC(dst, n)   asm volatile("tcgen05.alloc.cta_group::1.sync.aligned.shared::cta.b32 [%0], %1;" :: "r"(dst), "r"(n) : "memory")
#define TC_RELINQ()        asm volatile("tcgen05.relinquish_alloc_permit.cta_group::1.sync.aligned;")
#define TC_DEALLOC(t, n)   asm volatile("tcgen05.dealloc.cta_group::1.sync.aligned.b32 %0, %1;" :: "r"(t), "r"(n))
#define TC_WAIT_LD()       asm volatile("tcgen05.wait::ld.sync.aligned;" ::: "memory")
#define LDTM_X32(r, a) \
    asm volatile("tcgen05.ld.sync.aligned.32x32b.x32.b32 " \
        "{%0,%1,%2,%3,%4,%5,%6,%7,%8,%9,%10,%11,%12,%13,%14,%15," \
        "%16,%17,%18,%19,%20,%21,%22,%23,%24,%25,%26,%27,%28,%29,%30,%31}, [%32];" \
        : "=r"((r)[0]),"=r"((r)[1]),"=r"((r)[2]),"=r"((r)[3]),"=r"((r)[4]),"=r"((r)[5]),"=r"((r)[6]),"=r"((r)[7]), \
          "=r"((r)[8]),"=r"((r)[9]),"=r"((r)[10]),"=r"((r)[11]),"=r"((r)[12]),"=r"((r)[13]),"=r"((r)[14]),"=r"((r)[15]), \
          "=r"((r)[16]),"=r"((r)[17]),"=r"((r)[18]),"=r"((r)[19]),"=r"((r)[20]),"=r"((r)[21]),"=r"((r)[22]),"=r"((r)[23]), \
          "=r"((r)[24]),"=r"((r)[25]),"=r"((r)[26]),"=r"((r)[27]),"=r"((r)[28]),"=r"((r)[29]),"=r"((r)[30]),"=r"((r)[31]) \
        : "r"(a))

// MMA issue for one 128x512x32 tile (4 ksteps x 4 nchunks)
__device__ __forceinline__ void issue_tile(uint32_t sb, uint32_t a_off, uint32_t b_off,
                                           uint32_t tmem, bool first, uint32_t mbar) {
    const uint64_t ab = make_desc(sb + a_off);
    const uint64_t bb = make_desc(sb + b_off);
    if (elect_one()) {
#pragma unroll
        for (int ks = 0; ks < 4; ++ks) {
            const uint32_t en = (!first || ks > 0) ? 1u : 0u;
#pragma unroll
            for (int nc = 0; nc < 4; ++nc)
                mma_tf32(tmem + nc * 128, ab + ks * 2, bb + nc * 1024 + ks * 2,
                         IDESC_TF32, en);
        }
        tc_commit(mbar);
    }
}

// Fused epilogue: y = D + resid + bias; LN(y) -> dst; optionally fq from cols 0..7.
__device__ __forceinline__ void epilogue_ln(char* sm, uint32_t tmem,
                                            const float* __restrict__ resid,
                                            float* __restrict__ dst, int bm, int t,
                                            bool do_fq, const float* __restrict__ thF) {
    const int w = t >> 5, lane = t & 31;
    const int sp = w & 3, half = w >> 2;
    const int row_local = sp * 32 + lane;
    const int grow = bm + row_local;
    const float* xr = resid + (size_t)grow * E_DIM;
    const float* bias = (const float*)(sm + SM_PAR);
    const float* gam  = (const float*)(sm + SM_PAR + 2048);
    const float* bet  = (const float*)(sm + SM_PAR + 4096);
    float* redp = (float*)(sm + SM_RED);

    // pass 1: stats
    float s = 0.f, ss = 0.f;
#pragma unroll 1
    for (int ch = 0; ch < 8; ++ch) {
        const int colb = half * 256 + ch * 32;
        uint32_t r[32];
        LDTM_X32(r, tmem + colb);
        TC_WAIT_LD();
#pragma unroll
        for (int c4 = 0; c4 < 8; ++c4) {
            const float4 xv = *(const float4*)(xr + colb + c4 * 4);
            const float4 bv = *(const float4*)(bias + colb + c4 * 4);
            float y0 = __uint_as_float(r[c4 * 4 + 0]) + xv.x + bv.x;
            float y1 = __uint_as_float(r[c4 * 4 + 1]) + xv.y + bv.y;
            float y2 = __uint_as_float(r[c4 * 4 + 2]) + xv.z + bv.z;
            float y3 = __uint_as_float(r[c4 * 4 + 3]) + xv.w + bv.w;
            s += y0 + y1 + y2 + y3;
            ss = fmaf(y0, y0, fmaf(y1, y1, fmaf(y2, y2, fmaf(y3, y3, ss))));
        }
    }
    redp[row_local * 2 + half] = s;
    redp[256 + row_local * 2 + half] = ss;
    __syncthreads();
    const float st  = redp[row_local * 2] + redp[row_local * 2 + 1];
    const float sst = redp[256 + row_local * 2] + redp[256 + row_local * 2 + 1];
    const float mu  = st * (1.0f / 512.0f);
    const float inv = rsqrtf(sst * (1.0f / 512.0f) - mu * mu + 1e-5f);

    // pass 2: normalize + store (coalesced via bounce)
    float* eb = (float*)(sm + SM_EP + w * 4608);  // [32][36]
    const int rbase = sp * 32;
#pragma unroll 1
    for (int ch = 0; ch < 8; ++ch) {
        const int colb = half * 256 + ch * 32;
        uint32_t r[32];
        LDTM_X32(r, tmem + colb);
        TC_WAIT_LD();
#pragma unroll
        for (int c4 = 0; c4 < 8; ++c4) {
            const float4 xv = *(const float4*)(xr + colb + c4 * 4);
            const float4 bv = *(const float4*)(bias + colb + c4 * 4);
            const float4 gv = *(const float4*)(gam + colb + c4 * 4);
            const float4 tv = *(const float4*)(bet + colb + c4 * 4);
            float4 o;
            o.x = (__uint_as_float(r[c4 * 4 + 0]) + xv.x + bv.x - mu) * inv * gv.x + tv.x;
            o.y = (__uint_as_float(r[c4 * 4 + 1]) + xv.y + bv.y - mu) * inv * gv.y + tv.y;
            o.z = (__uint_as_float(r[c4 * 4 + 2]) + xv.z + bv.z - mu) * inv * gv.z + tv.z;
            o.w = (__uint_as_float(r[c4 * 4 + 3]) + xv.w + bv.w - mu) * inv * gv.w + tv.w;
            *(float4*)(eb + lane * 36 + c4 * 4) = o;
        }
        if (do_fq && half == 0 && ch == 0) {
            const float4 o0 = *(const float4*)(eb + lane * 36);
            const float4 o1 = *(const float4*)(eb + lane * 36 + 4);
            float4 c0, c1;
            c0.x = cosf(o0.x + thF[0]); c0.y = cosf(o0.y + thF[1]);
            c0.z = cosf(o0.z + thF[2]); c0.w = cosf(o0.w + thF[3]);
            c1.x = cosf(o1.x + thF[4]); c1.y = cosf(o1.y + thF[5]);
            c1.z = cosf(o1.z + thF[6]); c1.w = cosf(o1.w + thF[7]);
            *(float4*)(g_fq + (size_t)grow * 8) = c0;
            *(float4*)(g_fq + (size_t)grow * 8 + 4) = c1;
        }
        __syncwarp();
#pragma unroll
        for (int j = 0; j < 32; ++j)
            dst[(size_t)(bm + rbase + j) * E_DIM + colb + lane] = eb[j * 36 + lane];
        __syncwarp();
    }
}
#endif  // HAS_TCGEN05

// ================= GEMM1 + LN1 fused =================
__global__ __launch_bounds__(256, 1)
void gemm1_tc(const float* __restrict__ x, const float* __restrict__ theta,
              const float* __restrict__ bc, const float* __restrict__ g1,
              const float* __restrict__ be1, const float* __restrict__ thF) {
#if HAS_TCGEN05
    extern __shared__ char sm[];
    const uint32_t sb = smem_u32(sm);
    const int t = threadIdx.x;
    const int bm = blockIdx.x * 128;

    if (t < 32) TC_ALLOC(sb + SM_TMEM, 512);
    if (t == 0) { mbar_init(sb + MB_MMA0, 1); mbar_init(sb + MB_MMA1, 1); }
    // stage params + theta
    ((float*)(sm + SM_PAR))[t] = bc[t];          ((float*)(sm + SM_PAR))[t + 256] = bc[t + 256];
    ((float*)(sm + SM_PAR + 2048))[t] = g1[t];   ((float*)(sm + SM_PAR + 2048))[t + 256] = g1[t + 256];
    ((float*)(sm + SM_PAR + 4096))[t] = be1[t];  ((float*)(sm + SM_PAR + 4096))[t + 256] = be1[t + 256];
    ((float*)(sm + SM_TH))[t] = theta[t];        ((float*)(sm + SM_TH))[t + 256] = theta[t + 256];
    __syncthreads();

    uint32_t tmem;
    asm volatile("ld.shared.b32 %0, [%1];" : "=r"(tmem) : "r"(sb + SM_TMEM));
    const float* th_s = (const float*)(sm + SM_TH);
    const char* bsrc = (const char*)g_Wcp;
    const int NIT = E_DIM / 32;  // 16

    auto copy_B = [&](int it, uint32_t Boff) {
        const char* s = bsrc + (size_t)it * 65536 + t * 16;
        const uint32_t d = sb + Boff + t * 16;
#pragma unroll
        for (int j = 0; j < 16; ++j)
            cp16(d + j * 4096, s + (size_t)j * 4096);
        CP_COMMIT();
    };
    auto gen_A = [&](int it, uint32_t Aoff) {
        const int k0 = it * 32;
#pragma unroll
        for (int j = 0; j < 4; ++j) {
            const int idx = t + j * 256;
            const int row = idx >> 3, q4 = idx & 7;
            const float4 v = *(const float4*)(x + (size_t)(bm + row) * E_DIM + k0 + q4 * 4);
            const float4 thv = *(const float4*)(th_s + k0 + q4 * 4);
            uint4 o;
            o.x = f2tf32(cosf(v.x + thv.x));
            o.y = f2tf32(cosf(v.y + thv.y));
            o.z = f2tf32(cosf(v.z + thv.z));
            o.w = f2tf32(cosf(v.w + thv.w));
            *(uint4*)(sm + Aoff + swz_off(row, q4)) = o;
        }
    };

    copy_B(0, SM_B0);
    gen_A(0, SM_A0);

    int phm[2] = {0, 0};
    for (int it = 0; it < NIT; ++it) {
        const int buf = it & 1, ob = buf ^ 1;
        if (it >= 1) { mbar_wait(sb + MB_MMA0 + ob * 8, phm[ob]); phm[ob] ^= 1; }
        if (it + 1 < NIT) {
            copy_B(it + 1, ob ? SM_B1 : SM_B0);
            gen_A(it + 1, ob ? SM_A1 : SM_A0);
            CP_WAIT(1);
        } else {
            CP_WAIT(0);
        }
        fence_proxy_async_cta();
        __syncthreads();
        if (t < 32)
            issue_tile(sb, buf ? SM_A1 : SM_A0, buf ? SM_B1 : SM_B0, tmem, it == 0,
                       sb + MB_MMA0 + buf * 8);
    }
    const int lb = (NIT - 1) & 1;
    mbar_wait(sb + MB_MMA0 + lb * 8, phm[lb]);
    tc_fence_after();
    __syncthreads();

    epilogue_ln(sm, tmem, x, g_x1, bm, t, true, thF);

    __syncthreads();
    if (t < 32) { TC_RELINQ(); TC_DEALLOC(tmem, 512); }
#endif
}

// ================= GEMM2 + LN2 fused =================
__global__ __launch_bounds__(256, 1)
void gemm2_tc(const float* __restrict__ W1, const float* __restrict__ b1,
              const float* __restrict__ b2, const float* __restrict__ g2,
              const float* __restrict__ be2, float* __restrict__ out) {
#if HAS_TCGEN05
    extern __shared__ char sm[];
    const uint32_t sb = smem_u32(sm);
    const int t = threadIdx.x;
    const int bm = blockIdx.x * 128;

    if (t < 32) TC_ALLOC(sb + SM_TMEM, 512);
    if (t == 0) { mbar_init(sb + MB_MMA0, 1); mbar_init(sb + MB_MMA1, 1); }
    ((float*)(sm + SM_PAR))[t] = b2[t];          ((float*)(sm + SM_PAR))[t + 256] = b2[t + 256];
    ((float*)(sm + SM_PAR + 2048))[t] = g2[t];   ((float*)(sm + SM_PAR + 2048))[t + 256] = g2[t + 256];
    ((float*)(sm + SM_PAR + 4096))[t] = be2[t];  ((float*)(sm + SM_PAR + 4096))[t + 256] = be2[t + 256];
    ((float4*)(sm + SM_TH))[t] = ((const float4*)(g_fq + (size_t)bm * 8))[t];  // fq 4KB
    __syncthreads();

    uint32_t tmem;
    asm volatile("ld.shared.b32 %0, [%1];" : "=r"(tmem) : "r"(sb + SM_TMEM));
    const char* bsrc = (const char*)g_W2p;
    const int NIT = FFN_DIM / 32;  // 64
    const int kl = t & 31;
    const int rb = (t >> 5) * 16;

    auto copy_B = [&](int it, uint32_t Boff) {
        const char* s = bsrc + (size_t)it * 65536 + t * 16;
        const uint32_t d = sb + Boff + t * 16;
#pragma unroll
        for (int j = 0; j < 16; ++j)
            cp16(d + j * 4096, s + (size_t)j * 4096);
        CP_COMMIT();
    };
    auto gen_A = [&](int it, uint32_t Aoff) {
        const int k0 = it * 32;
        const float4 w1a = *(const float4*)(W1 + (size_t)(k0 + kl) * 8);
        const float4 w1b = *(const float4*)(W1 + (size_t)(k0 + kl) * 8 + 4);
        const float b1v = b1[k0 + kl];
#pragma unroll
        for (int i = 0; i < 16; ++i) {
            const int r = rb + i;
            const float4 f0 = *(const float4*)(sm + SM_TH + r * 32);
            const float4 f1 = *(const float4*)(sm + SM_TH + r * 32 + 16);
            float h = b1v;
            h = fmaf(f0.x, w1a.x, h); h = fmaf(f0.y, w1a.y, h);
            h = fmaf(f0.z, w1a.z, h); h = fmaf(f0.w, w1a.w, h);
            h = fmaf(f1.x, w1b.x, h); h = fmaf(f1.y, w1b.y, h);
            h = fmaf(f1.z, w1b.z, h); h = fmaf(f1.w, w1b.w, h);
            h = fmaxf(h, 0.0f);
            *(uint32_t*)(sm + Aoff + (uint32_t)(r * 128 + (((kl >> 2) ^ (r & 7)) * 16 + (kl & 3) * 4))) = f2tf32(h);
        }
    };

    copy_B(0, SM_B0);
    gen_A(0, SM_A0);

    int phm[2] = {0, 0};
    for (int it = 0; it < NIT; ++it) {
        const int buf = it & 1, ob = buf ^ 1;
        if (it >= 1) { mbar_wait(sb + MB_MMA0 + ob * 8, phm[ob]); phm[ob] ^= 1; }
        if (it + 1 < NIT) {
            copy_B(it + 1, ob ? SM_B1 : SM_B0);
            gen_A(it + 1, ob ? SM_A1 : SM_A0);
            CP_WAIT(1);
        } else {
            CP_WAIT(0);
        }
        fence_proxy_async_cta();
        __syncthreads();
        if (t < 32)
            issue_tile(sb, buf ? SM_A1 : SM_A0, buf ? SM_B1 : SM_B0, tmem, it == 0,
                       sb + MB_MMA0 + buf * 8);
    }
    const int lb = (NIT - 1) & 1;
    mbar_wait(sb + MB_MMA0 + lb * 8, phm[lb]);
    tc_fence_after();
    __syncthreads();

    epilogue_ln(sm, tmem, g_x1, out, bm, t, false, nullptr);

    __syncthreads();
    if (t < 32) { TC_RELINQ(); TC_DEALLOC(tmem, 512); }
#endif
}

// ================= launch =================
extern "C" void kernel_launch(void* const* d_in, const int* in_sizes, int n_in,
                              void* d_out, int out_size) {
    const float* x   = (const float*)d_in[0];
    const float* thA = (const float*)d_in[1];
    const float* Wc  = (const float*)d_in[2];
    const float* bc  = (const float*)d_in[3];
    const float* g1  = (const float*)d_in[4];
    const float* be1 = (const float*)d_in[5];
    const float* thF = (const float*)d_in[6];
    const float* W1  = (const float*)d_in[7];
    const float* b1  = (const float*)d_in[8];
    const float* W2  = (const float*)d_in[9];
    const float* b2  = (const float*)d_in[10];
    const float* g2  = (const float*)d_in[11];
    const float* be2 = (const float*)d_in[12];
    float* out = (float*)d_out;

    cudaFuncSetAttribute(gemm1_tc, cudaFuncAttributeMaxDynamicSharedMemorySize, SMEM_BYTES);
    cudaFuncSetAttribute(gemm2_tc, cudaFuncAttributeMaxDynamicSharedMemorySize, SMEM_BYTES);

    // pack weights (tf32 + SW128 smem image), cheap: 5MB total
    repack_kernel<<<(512 * E_DIM / 4 + 255) / 256, 256>>>(Wc, E_DIM, 0);
    repack_kernel<<<(512 * FFN_DIM / 4 + 255) / 256, 256>>>(W2, FFN_DIM, 1);

    gemm1_tc<<<M_TOTAL / 128, 256, SMEM_BYTES>>>(x, thA, bc, g1, be1, thF);
    gemm2_tc<<<M_TOTAL / 128, 256, SMEM_BYTES>>>(W1, b1, b2, g2, be2, out);
}

// round 8
// speedup vs baseline: 4.5031x; 1.0481x over previous
#include <cuda_runtime.h>
#include <cstdint>

#define M_TOTAL 32768
#define E_DIM   512
#define FFN_DIM 2048

#if defined(__CUDA_ARCH__) && defined(__CUDA_ARCH_FEAT_SM103_ALL)
#define HAS_TCGEN05 1
#else
#define HAS_TCGEN05 0
#endif

// scratch (device globals, allocation-free)
__device__ float g_x1[(size_t)M_TOTAL * E_DIM];   // LN1 out
__device__ float g_fq[(size_t)M_TOTAL * 8];       // cos(x1[:, :8] + theta_ffn)
// packed weights: tf32, SW128 smem image, 64KB per 512x32 k-tile
__device__ uint4 g_Wcp[65536];                    // Wc: 16 tiles x 64KB = 1MB
__device__ uint4 g_W2p[262144];                   // W2: 64 tiles x 64KB = 4MB

// ---------------- smem layout (dynamic) ----------------
#define SM_TMEM  0
#define MB_MMA0  16
#define MB_MMA1  24
#define SM_RED   64          // 512 floats: s[128][2], ss[128][2]
#define SM_PAR   2112        // 3 x 512 floats (bias, gamma, beta)
#define SM_TH    8256        // gemm1: theta 512 floats / gemm2: fq 4KB
#define SM_W1A   12352       // gemm2: staged W1 slice (1KB) + b1 slice (128B), buf0
#define SM_W1B   13568       // buf1
#define SM_A0    16384       // 16KB
#define SM_A1    32768       // 16KB
#define SM_B0    49152       // 64KB
#define SM_B1    114688      // 64KB
#define SM_X0    180224      // gemm1: staged x slice 16KB, buf0
#define SM_X1    196608      // buf1
#define SMEM_BYTES 212992
#define SM_EP    16384       // epilogue bounce (reuses A/B space post-mainloop)

// idesc: dtype=F32(1<<4), atype=TF32(2<<7), btype=TF32(2<<10), N=128(16<<17), M=128(8<<24)
#define IDESC_TF32 ((1u<<4)|(2u<<7)|(2u<<10)|(16u<<17)|(8u<<24))

// ---------------- common helpers (all PTX stages) ----------------
__device__ __forceinline__ uint32_t smem_u32(const void* p) {
    uint32_t a;
    asm("{ .reg .u64 t; cvta.to.shared.u64 t, %1; cvt.u32.u64 %0, t; }" : "=r"(a) : "l"(p));
    return a;
}
__device__ __forceinline__ uint32_t f2tf32(float f) {
    uint32_t r;
    asm("cvt.rna.tf32.f32 %0, %1;" : "=r"(r) : "f"(f));
    return r;
}
// swizzled byte offset of 16B group q16 within row (128B rows, SW128)
__device__ __forceinline__ uint32_t swz_off(int row, int q16) {
    return (uint32_t)(row * 128 + ((q16 ^ (row & 7)) * 16));
}

// ================= weight repack =================
__global__ __launch_bounds__(256) void repack_kernel(const float* __restrict__ src,
                                                     int K, int which) {
    uint4* dst = which ? g_W2p : g_Wcp;
    const int g = blockIdx.x * blockDim.x + threadIdx.x;   // one 16B group
    const int total = 512 * K / 4;
    if (g >= total) return;
    const int q16 = g & 7;
    const int row = (g >> 3) & 511;
    const int tile = g >> 12;
    const float4 v = *(const float4*)(src + (size_t)row * K + tile * 32 + q16 * 4);
    uint4 o;
    o.x = f2tf32(v.x); o.y = f2tf32(v.y); o.z = f2tf32(v.z); o.w = f2tf32(v.w);
    *(uint4*)((char*)dst + (size_t)tile * 65536 + swz_off(row, q16)) = o;
}

#if HAS_TCGEN05
// ---------------- tcgen05 helpers (sm_103a only) ----------------
__device__ __forceinline__ uint32_t elect_one() {
    uint32_t p;
    asm volatile("{ .reg .pred p; elect.sync _|p, 0xFFFFFFFF; selp.b32 %0, 1, 0, p; }" : "=r"(p));
    return p;
}
__device__ __forceinline__ uint64_t make_desc(uint32_t addr) {
    return (uint64_t(2) << 61) | (uint64_t(1) << 46) | (uint64_t(64) << 32) |
           (uint64_t(1) << 16) | ((addr >> 4) & 0x3FFFu);
}
__device__ __forceinline__ void mma_tf32(uint32_t d, uint64_t ad, uint64_t bd,
                                         uint32_t idesc, uint32_t en) {
    asm volatile(
        "{\n\t.reg .pred p;\n\tsetp.ne.u32 p, %5, 0;\n\t"
        "tcgen05.mma.cta_group::1.kind::tf32 [%0], %1, %2, %3, {%4, %4, %4, %4}, p;\n\t}"
        :: "r"(d), "l"(ad), "l"(bd), "r"(idesc), "r"(0u), "r"(en) : "memory");
}
__device__ __forceinline__ void tc_commit(uint32_t mbar) {
    asm volatile(
        "tcgen05.commit.cta_group::1.mbarrier::arrive::one.shared::cluster.b64 [%0];"
        :: "r"(mbar) : "memory");
}
__device__ __forceinline__ void mbar_init(uint32_t mbar, uint32_t cnt) {
    asm volatile("mbarrier.init.shared.b64 [%0], %1;" :: "r"(mbar), "r"(cnt) : "memory");
}
__device__ __forceinline__ void mbar_wait(uint32_t mbar, uint32_t ph) {
    asm volatile(
        "{\n\t.reg .pred P1;\n\t"
        "W_%=:\n\t"
        "mbarrier.try_wait.parity.acquire.cta.shared::cta.b64 P1, [%0], %1, 0x989680;\n\t"
        "@P1 bra D_%=;\n\t"
        "bra W_%=;\n\t"
        "D_%=:\n\t}"
        :: "r"(mbar), "r"(ph) : "memory");
}
__device__ __forceinline__ void fence_proxy_async_cta() {
    asm volatile("fence.proxy.async.shared::cta;" ::: "memory");
}
__device__ __forceinline__ void tc_fence_after() {
    asm volatile("tcgen05.fence::after_thread_sync;" ::: "memory");
}
// cp.async (LDGSTS) 16B copy + group fences
__device__ __forceinline__ void cp16(uint32_t dst, const void* src) {
    asm volatile("cp.async.cg.shared.global [%0], [%1], 16;" :: "r"(dst), "l"(src) : "memory");
}
#define CP_COMMIT() asm volatile("cp.async.commit_group;" ::: "memory")
#define CP_WAIT(n)  asm volatile("cp.async.wait_group %0;" :: "n"(n) : "memory")

#define TC_ALLOC(dst, n)   asm volatile("tcgen05.alloc.cta_group::1.sync.aligned.shared::cta.b32 [%0], %1;" :: "r"(dst), "r"(n) : "memory")
#define TC_RELINQ()        asm volatile("tcgen05.relinquish_alloc_permit.cta_group::1.sync.aligned;")
#define TC_DEALLOC(t, n)   asm volatile("tcgen05.dealloc.cta_group::1.sync.aligned.b32 %0, %1;" :: "r"(t), "r"(n))
#define TC_WAIT_LD()       asm volatile("tcgen05.wait::ld.sync.aligned;" ::: "memory")
#define LDTM_X32(r, a) \
    asm volatile("tcgen05.ld.sync.aligned.32x32b.x32.b32 " \
        "{%0,%1,%2,%3,%4,%5,%6,%7,%8,%9,%10,%11,%12,%13,%14,%15," \
        "%16,%17,%18,%19,%20,%21,%22,%23,%24,%25,%26,%27,%28,%29,%30,%31}, [%32];" \
        : "=r"((r)[0]),"=r"((r)[1]),"=r"((r)[2]),"=r"((r)[3]),"=r"((r)[4]),"=r"((r)[5]),"=r"((r)[6]),"=r"((r)[7]), \
          "=r"((r)[8]),"=r"((r)[9]),"=r"((r)[10]),"=r"((r)[11]),"=r"((r)[12]),"=r"((r)[13]),"=r"((r)[14]),"=r"((r)[15]), \
          "=r"((r)[16]),"=r"((r)[17]),"=r"((r)[18]),"=r"((r)[19]),"=r"((r)[20]),"=r"((r)[21]),"=r"((r)[22]),"=r"((r)[23]), \
          "=r"((r)[24]),"=r"((r)[25]),"=r"((r)[26]),"=r"((r)[27]),"=r"((r)[28]),"=r"((r)[29]),"=r"((r)[30]),"=r"((r)[31]) \
        : "r"(a))

// MMA issue for one 128x512x32 tile (4 ksteps x 4 nchunks)
__device__ __forceinline__ void issue_tile(uint32_t sb, uint32_t a_off, uint32_t b_off,
                                           uint32_t tmem, bool first, uint32_t mbar) {
    const uint64_t ab = make_desc(sb + a_off);
    const uint64_t bb = make_desc(sb + b_off);
    if (elect_one()) {
#pragma unroll
        for (int ks = 0; ks < 4; ++ks) {
            const uint32_t en = (!first || ks > 0) ? 1u : 0u;
#pragma unroll
            for (int nc = 0; nc < 4; ++nc)
                mma_tf32(tmem + nc * 128, ab + ks * 2, bb + nc * 1024 + ks * 2,
                         IDESC_TF32, en);
        }
        tc_commit(mbar);
    }
}

// Fused epilogue: y = D + resid + bias; LN(y) -> dst; optionally fq from cols 0..7.
__device__ __forceinline__ void epilogue_ln(char* sm, uint32_t tmem,
                                            const float* __restrict__ resid,
                                            float* __restrict__ dst, int bm, int t,
                                            bool do_fq, const float* __restrict__ thF) {
    const int w = t >> 5, lane = t & 31;
    const int sp = w & 3, half = w >> 2;
    const int row_local = sp * 32 + lane;
    const int grow = bm + row_local;
    const float* xr = resid + (size_t)grow * E_DIM;
    const float* bias = (const float*)(sm + SM_PAR);
    const float* gam  = (const float*)(sm + SM_PAR + 2048);
    const float* bet  = (const float*)(sm + SM_PAR + 4096);
    float* redp = (float*)(sm + SM_RED);

    // pass 1: stats
    float s = 0.f, ss = 0.f;
#pragma unroll 1
    for (int ch = 0; ch < 8; ++ch) {
        const int colb = half * 256 + ch * 32;
        uint32_t r[32];
        LDTM_X32(r, tmem + colb);
        TC_WAIT_LD();
#pragma unroll
        for (int c4 = 0; c4 < 8; ++c4) {
            const float4 xv = *(const float4*)(xr + colb + c4 * 4);
            const float4 bv = *(const float4*)(bias + colb + c4 * 4);
            float y0 = __uint_as_float(r[c4 * 4 + 0]) + xv.x + bv.x;
            float y1 = __uint_as_float(r[c4 * 4 + 1]) + xv.y + bv.y;
            float y2 = __uint_as_float(r[c4 * 4 + 2]) + xv.z + bv.z;
            float y3 = __uint_as_float(r[c4 * 4 + 3]) + xv.w + bv.w;
            s += y0 + y1 + y2 + y3;
            ss = fmaf(y0, y0, fmaf(y1, y1, fmaf(y2, y2, fmaf(y3, y3, ss))));
        }
    }
    redp[row_local * 2 + half] = s;
    redp[256 + row_local * 2 + half] = ss;
    __syncthreads();
    const float st  = redp[row_local * 2] + redp[row_local * 2 + 1];
    const float sst = redp[256 + row_local * 2] + redp[256 + row_local * 2 + 1];
    const float mu  = st * (1.0f / 512.0f);
    const float inv = rsqrtf(sst * (1.0f / 512.0f) - mu * mu + 1e-5f);

    // pass 2: normalize + store (coalesced via bounce)
    float* eb = (float*)(sm + SM_EP + w * 4608);  // [32][36]
    const int rbase = sp * 32;
#pragma unroll 1
    for (int ch = 0; ch < 8; ++ch) {
        const int colb = half * 256 + ch * 32;
        uint32_t r[32];
        LDTM_X32(r, tmem + colb);
        TC_WAIT_LD();
#pragma unroll
        for (int c4 = 0; c4 < 8; ++c4) {
            const float4 xv = *(const float4*)(xr + colb + c4 * 4);
            const float4 bv = *(const float4*)(bias + colb + c4 * 4);
            const float4 gv = *(const float4*)(gam + colb + c4 * 4);
            const float4 tv = *(const float4*)(bet + colb + c4 * 4);
            float4 o;
            o.x = (__uint_as_float(r[c4 * 4 + 0]) + xv.x + bv.x - mu) * inv * gv.x + tv.x;
            o.y = (__uint_as_float(r[c4 * 4 + 1]) + xv.y + bv.y - mu) * inv * gv.y + tv.y;
            o.z = (__uint_as_float(r[c4 * 4 + 2]) + xv.z + bv.z - mu) * inv * gv.z + tv.z;
            o.w = (__uint_as_float(r[c4 * 4 + 3]) + xv.w + bv.w - mu) * inv * gv.w + tv.w;
            *(float4*)(eb + lane * 36 + c4 * 4) = o;
        }
        if (do_fq && half == 0 && ch == 0) {
            const float4 o0 = *(const float4*)(eb + lane * 36);
            const float4 o1 = *(const float4*)(eb + lane * 36 + 4);
            float4 c0, c1;
            c0.x = cosf(o0.x + thF[0]); c0.y = cosf(o0.y + thF[1]);
            c0.z = cosf(o0.z + thF[2]); c0.w = cosf(o0.w + thF[3]);
            c1.x = cosf(o1.x + thF[4]); c1.y = cosf(o1.y + thF[5]);
            c1.z = cosf(o1.z + thF[6]); c1.w = cosf(o1.w + thF[7]);
            *(float4*)(g_fq + (size_t)grow * 8) = c0;
            *(float4*)(g_fq + (size_t)grow * 8 + 4) = c1;
        }
        __syncwarp();
#pragma unroll
        for (int j = 0; j < 32; ++j)
            dst[(size_t)(bm + rbase + j) * E_DIM + colb + lane] = eb[j * 36 + lane];
        __syncwarp();
    }
}
#endif  // HAS_TCGEN05

// ================= GEMM1 + LN1 fused =================
__global__ __launch_bounds__(256, 1)
void gemm1_tc(const float* __restrict__ x, const float* __restrict__ theta,
              const float* __restrict__ bc, const float* __restrict__ g1,
              const float* __restrict__ be1, const float* __restrict__ thF) {
#if HAS_TCGEN05
    extern __shared__ char sm[];
    const uint32_t sb = smem_u32(sm);
    const int t = threadIdx.x;
    const int bm = blockIdx.x * 128;

    if (t < 32) TC_ALLOC(sb + SM_TMEM, 512);
    if (t == 0) { mbar_init(sb + MB_MMA0, 1); mbar_init(sb + MB_MMA1, 1); }
    ((float*)(sm + SM_PAR))[t] = bc[t];          ((float*)(sm + SM_PAR))[t + 256] = bc[t + 256];
    ((float*)(sm + SM_PAR + 2048))[t] = g1[t];   ((float*)(sm + SM_PAR + 2048))[t + 256] = g1[t + 256];
    ((float*)(sm + SM_PAR + 4096))[t] = be1[t];  ((float*)(sm + SM_PAR + 4096))[t + 256] = be1[t + 256];
    ((float*)(sm + SM_TH))[t] = theta[t];        ((float*)(sm + SM_TH))[t + 256] = theta[t + 256];
    __syncthreads();

    uint32_t tmem;
    asm volatile("ld.shared.b32 %0, [%1];" : "=r"(tmem) : "r"(sb + SM_TMEM));
    const float* th_s = (const float*)(sm + SM_TH);
    const char* bsrc = (const char*)g_Wcp;
    const int NIT = E_DIM / 32;  // 16

    // stage B tile + x slice for iteration `it`
    auto copy_tiles = [&](int it, uint32_t Boff, uint32_t Xoff) {
        const char* s = bsrc + (size_t)it * 65536 + t * 16;
        const uint32_t d = sb + Boff + t * 16;
#pragma unroll
        for (int j = 0; j < 16; ++j)
            cp16(d + j * 4096, s + (size_t)j * 4096);
        const int k0 = it * 32;
#pragma unroll
        for (int j = 0; j < 4; ++j) {
            const int g = t + j * 256;
            const int row = g >> 3, q4 = g & 7;
            cp16(sb + Xoff + g * 16, x + (size_t)(bm + row) * E_DIM + k0 + q4 * 4);
        }
        CP_COMMIT();
    };
    // A tile from staged x (smem-only)
    auto gen_A = [&](int it, uint32_t Aoff, uint32_t Xoff) {
        const int k0 = it * 32;
#pragma unroll
        for (int j = 0; j < 4; ++j) {
            const int idx = t + j * 256;
            const int row = idx >> 3, q4 = idx & 7;
            const float4 v = *(const float4*)(sm + Xoff + idx * 16);
            const float4 thv = *(const float4*)(th_s + k0 + q4 * 4);
            uint4 o;
            o.x = f2tf32(cosf(v.x + thv.x));
            o.y = f2tf32(cosf(v.y + thv.y));
            o.z = f2tf32(cosf(v.z + thv.z));
            o.w = f2tf32(cosf(v.w + thv.w));
            *(uint4*)(sm + Aoff + swz_off(row, q4)) = o;
        }
    };

    copy_tiles(0, SM_B0, SM_X0);

    int phm[2] = {0, 0};
    for (int it = 0; it < NIT; ++it) {
        const int buf = it & 1, ob = buf ^ 1;
        CP_WAIT(0);
        __syncthreads();
        gen_A(it, buf ? SM_A1 : SM_A0, buf ? SM_X1 : SM_X0);
        fence_proxy_async_cta();
        __syncthreads();
        if (t < 32)
            issue_tile(sb, buf ? SM_A1 : SM_A0, buf ? SM_B1 : SM_B0, tmem, it == 0,
                       sb + MB_MMA0 + buf * 8);
        if (it >= 1) { mbar_wait(sb + MB_MMA0 + ob * 8, phm[ob]); phm[ob] ^= 1; }
        if (it + 1 < NIT)
            copy_tiles(it + 1, ob ? SM_B1 : SM_B0, ob ? SM_X1 : SM_X0);
    }
    const int lb = (NIT - 1) & 1;
    mbar_wait(sb + MB_MMA0 + lb * 8, phm[lb]);
    tc_fence_after();
    __syncthreads();

    epilogue_ln(sm, tmem, x, g_x1, bm, t, true, thF);

    __syncthreads();
    if (t < 32) { TC_RELINQ(); TC_DEALLOC(tmem, 512); }
#endif
}

// ================= GEMM2 + LN2 fused =================
__global__ __launch_bounds__(256, 1)
void gemm2_tc(const float* __restrict__ W1, const float* __restrict__ b1,
              const float* __restrict__ b2, const float* __restrict__ g2,
              const float* __restrict__ be2, float* __restrict__ out) {
#if HAS_TCGEN05
    extern __shared__ char sm[];
    const uint32_t sb = smem_u32(sm);
    const int t = threadIdx.x;
    const int bm = blockIdx.x * 128;

    if (t < 32) TC_ALLOC(sb + SM_TMEM, 512);
    if (t == 0) { mbar_init(sb + MB_MMA0, 1); mbar_init(sb + MB_MMA1, 1); }
    ((float*)(sm + SM_PAR))[t] = b2[t];          ((float*)(sm + SM_PAR))[t + 256] = b2[t + 256];
    ((float*)(sm + SM_PAR + 2048))[t] = g2[t];   ((float*)(sm + SM_PAR + 2048))[t + 256] = g2[t + 256];
    ((float*)(sm + SM_PAR + 4096))[t] = be2[t];  ((float*)(sm + SM_PAR + 4096))[t + 256] = be2[t + 256];
    ((float4*)(sm + SM_TH))[t] = ((const float4*)(g_fq + (size_t)bm * 8))[t];  // fq 4KB
    __syncthreads();

    uint32_t tmem;
    asm volatile("ld.shared.b32 %0, [%1];" : "=r"(tmem) : "r"(sb + SM_TMEM));
    const char* bsrc = (const char*)g_W2p;
    const int NIT = FFN_DIM / 32;  // 64
    const int kl = t & 31;
    const int rb = (t >> 5) * 16;

    // stage B tile + W1/b1 slice for iteration `it`
    auto copy_tiles = [&](int it, uint32_t Boff, uint32_t Woff) {
        const char* s = bsrc + (size_t)it * 65536 + t * 16;
        const uint32_t d = sb + Boff + t * 16;
#pragma unroll
        for (int j = 0; j < 16; ++j)
            cp16(d + j * 4096, s + (size_t)j * 4096);
        const int k0 = it * 32;
        if (t < 64) {               // W1 rows k0..k0+31: 32x8 floats = 1KB
            const int row = t >> 1, half = t & 1;
            cp16(sb + Woff + t * 16, W1 + (size_t)(k0 + row) * 8 + half * 4);
        } else if (t < 72) {        // b1 slice: 32 floats
            cp16(sb + Woff + 1024 + (t - 64) * 16, b1 + k0 + (t - 64) * 4);
        }
        CP_COMMIT();
    };
    // A tile: h = relu(b1 + fq.W1), smem-only inputs
    auto gen_A = [&](uint32_t Aoff, uint32_t Woff) {
        const float4 w1a = *(const float4*)(sm + Woff + kl * 32);
        const float4 w1b = *(const float4*)(sm + Woff + kl * 32 + 16);
        const float b1v = *(const float*)(sm + Woff + 1024 + kl * 4);
#pragma unroll
        for (int i = 0; i < 16; ++i) {
            const int r = rb + i;
            const float4 f0 = *(const float4*)(sm + SM_TH + r * 32);
            const float4 f1 = *(const float4*)(sm + SM_TH + r * 32 + 16);
            float h = b1v;
            h = fmaf(f0.x, w1a.x, h); h = fmaf(f0.y, w1a.y, h);
            h = fmaf(f0.z, w1a.z, h); h = fmaf(f0.w, w1a.w, h);
            h = fmaf(f1.x, w1b.x, h); h = fmaf(f1.y, w1b.y, h);
            h = fmaf(f1.z, w1b.z, h); h = fmaf(f1.w, w1b.w, h);
            h = fmaxf(h, 0.0f);
            *(uint32_t*)(sm + Aoff + (uint32_t)(r * 128 + (((kl >> 2) ^ (r & 7)) * 16 + (kl & 3) * 4))) = f2tf32(h);
        }
    };

    copy_tiles(0, SM_B0, SM_W1A);

    int phm[2] = {0, 0};
    for (int it = 0; it < NIT; ++it) {
        const int buf = it & 1, ob = buf ^ 1;
        CP_WAIT(0);
        __syncthreads();
        gen_A(buf ? SM_A1 : SM_A0, buf ? SM_W1B : SM_W1A);
        fence_proxy_async_cta();
        __syncthreads();
        if (t < 32)
            issue_tile(sb, buf ? SM_A1 : SM_A0, buf ? SM_B1 : SM_B0, tmem, it == 0,
                       sb + MB_MMA0 + buf * 8);
        if (it >= 1) { mbar_wait(sb + MB_MMA0 + ob * 8, phm[ob]); phm[ob] ^= 1; }
        if (it + 1 < NIT)
            copy_tiles(it + 1, ob ? SM_B1 : SM_B0, ob ? SM_W1B : SM_W1A);
    }
    const int lb = (NIT - 1) & 1;
    mbar_wait(sb + MB_MMA0 + lb * 8, phm[lb]);
    tc_fence_after();
    __syncthreads();

    epilogue_ln(sm, tmem, g_x1, out, bm, t, false, nullptr);

    __syncthreads();
    if (t < 32) { TC_RELINQ(); TC_DEALLOC(tmem, 512); }
#endif
}

// ================= launch =================
extern "C" void kernel_launch(void* const* d_in, const int* in_sizes, int n_in,
                              void* d_out, int out_size) {
    const float* x   = (const float*)d_in[0];
    const float* thA = (const float*)d_in[1];
    const float* Wc  = (const float*)d_in[2];
    const float* bc  = (const float*)d_in[3];
    const float* g1  = (const float*)d_in[4];
    const float* be1 = (const float*)d_in[5];
    const float* thF = (const float*)d_in[6];
    const float* W1  = (const float*)d_in[7];
    const float* b1  = (const float*)d_in[8];
    const float* W2  = (const float*)d_in[9];
    const float* b2  = (const float*)d_in[10];
    const float* g2  = (const float*)d_in[11];
    const float* be2 = (const float*)d_in[12];
    float* out = (float*)d_out;

    cudaFuncSetAttribute(gemm1_tc, cudaFuncAttributeMaxDynamicSharedMemorySize, SMEM_BYTES);
    cudaFuncSetAttribute(gemm2_tc, cudaFuncAttributeMaxDynamicSharedMemorySize, SMEM_BYTES);

    repack_kernel<<<(512 * E_DIM / 4 + 255) / 256, 256>>>(Wc, E_DIM, 0);
    repack_kernel<<<(512 * FFN_DIM / 4 + 255) / 256, 256>>>(W2, FFN_DIM, 1);

    gemm1_tc<<<M_TOTAL / 128, 256, SMEM_BYTES>>>(x, thA, bc, g1, be1, thF);
    gemm2_tc<<<M_TOTAL / 128, 256, SMEM_BYTES>>>(W1, b1, b2, g2, be2, out);
}

// round 9
// speedup vs baseline: 4.7428x; 1.0532x over previous
#include <cuda_runtime.h>
#include <cstdint>

#define M_TOTAL 32768
#define E_DIM   512
#define FFN_DIM 2048

#if defined(__CUDA_ARCH__) && defined(__CUDA_ARCH_FEAT_SM103_ALL)
#define HAS_TCGEN05 1
#else
#define HAS_TCGEN05 0
#endif

// scratch (device globals, allocation-free)
__device__ float g_x1[(size_t)M_TOTAL * E_DIM];   // LN1 out
__device__ float g_fq[(size_t)M_TOTAL * 8];       // cos(x1[:, :8] + theta_ffn)
// packed weights: tf32, SW128 smem image, 64KB per 512x32 k-tile
__device__ uint4 g_Wcp[65536];                    // Wc: 16 tiles x 64KB = 1MB
__device__ uint4 g_W2p[262144];                   // W2: 64 tiles x 64KB = 4MB

// ---------------- smem layout (dynamic) ----------------
#define SM_TMEM   0
#define MB_FULL0  16
#define MB_FULL1  24
#define MB_EMPTY0 32
#define MB_EMPTY1 40
#define MB_FIN    48
#define SM_RED    64          // 512 floats: s[128][2], ss[128][2]
#define SM_PAR    2112        // 3 x 512 floats (bias, gamma, beta)
#define SM_TH     8256        // gemm1: theta 512 floats / gemm2: fq 4KB
#define SM_W1A    12352       // gemm2: staged W1 slice (1KB) + b1 slice (128B), buf0
#define SM_W1B    13568       // buf1
#define SM_A0     16384       // 16KB
#define SM_A1     32768       // 16KB
#define SM_B0     49152       // 64KB
#define SM_B1     114688      // 64KB
#define SM_X0     180224      // gemm1: staged x slice 16KB, buf0
#define SM_X1     196608      // buf1
#define SMEM_BYTES 212992
#define SM_EP     16384       // epilogue bounce (reuses A/B space post-mainloop)

// idesc: dtype=F32(1<<4), atype=TF32(2<<7), btype=TF32(2<<10), N=128(16<<17), M=128(8<<24)
#define IDESC_TF32 ((1u<<4)|(2u<<7)|(2u<<10)|(16u<<17)|(8u<<24))

// ---------------- common helpers (all PTX stages) ----------------
__device__ __forceinline__ uint32_t smem_u32(const void* p) {
    uint32_t a;
    asm("{ .reg .u64 t; cvta.to.shared.u64 t, %1; cvt.u32.u64 %0, t; }" : "=r"(a) : "l"(p));
    return a;
}
__device__ __forceinline__ uint32_t f2tf32(float f) {
    uint32_t r;
    asm("cvt.rna.tf32.f32 %0, %1;" : "=r"(r) : "f"(f));
    return r;
}
// swizzled byte offset of 16B group q16 within row (128B rows, SW128)
__device__ __forceinline__ uint32_t swz_off(int row, int q16) {
    return (uint32_t)(row * 128 + ((q16 ^ (row & 7)) * 16));
}

// ================= weight repack =================
__global__ __launch_bounds__(256) void repack_kernel(const float* __restrict__ src,
                                                     int K, int which) {
    uint4* dst = which ? g_W2p : g_Wcp;
    const int g = blockIdx.x * blockDim.x + threadIdx.x;   // one 16B group
    const int total = 512 * K / 4;
    if (g >= total) return;
    const int q16 = g & 7;
    const int row = (g >> 3) & 511;
    const int tile = g >> 12;
    const float4 v = *(const float4*)(src + (size_t)row * K + tile * 32 + q16 * 4);
    uint4 o;
    o.x = f2tf32(v.x); o.y = f2tf32(v.y); o.z = f2tf32(v.z); o.w = f2tf32(v.w);
    *(uint4*)((char*)dst + (size_t)tile * 65536 + swz_off(row, q16)) = o;
}

#if HAS_TCGEN05
// ---------------- tcgen05 helpers (sm_103a only) ----------------
__device__ __forceinline__ uint32_t elect_one() {
    uint32_t p;
    asm volatile("{ .reg .pred p; elect.sync _|p, 0xFFFFFFFF; selp.b32 %0, 1, 0, p; }" : "=r"(p));
    return p;
}
__device__ __forceinline__ uint64_t make_desc(uint32_t addr) {
    return (uint64_t(2) << 61) | (uint64_t(1) << 46) | (uint64_t(64) << 32) |
           (uint64_t(1) << 16) | ((addr >> 4) & 0x3FFFu);
}
__device__ __forceinline__ void mma_tf32(uint32_t d, uint64_t ad, uint64_t bd,
                                         uint32_t idesc, uint32_t en) {
    asm volatile(
        "{\n\t.reg .pred p;\n\tsetp.ne.u32 p, %5, 0;\n\t"
        "tcgen05.mma.cta_group::1.kind::tf32 [%0], %1, %2, %3, {%4, %4, %4, %4}, p;\n\t}"
        :: "r"(d), "l"(ad), "l"(bd), "r"(idesc), "r"(0u), "r"(en) : "memory");
}
__device__ __forceinline__ void tc_commit(uint32_t mbar) {
    asm volatile(
        "tcgen05.commit.cta_group::1.mbarrier::arrive::one.shared::cluster.b64 [%0];"
        :: "r"(mbar) : "memory");
}
__device__ __forceinline__ void mbar_init(uint32_t mbar, uint32_t cnt) {
    asm volatile("mbarrier.init.shared.b64 [%0], %1;" :: "r"(mbar), "r"(cnt) : "memory");
}
__device__ __forceinline__ void mbar_arrive(uint32_t mbar) {
    asm volatile("mbarrier.arrive.shared.b64 _, [%0];" :: "r"(mbar) : "memory");
}
__device__ __forceinline__ void mbar_wait(uint32_t mbar, uint32_t ph) {
    asm volatile(
        "{\n\t.reg .pred P1;\n\t"
        "W_%=:\n\t"
        "mbarrier.try_wait.parity.acquire.cta.shared::cta.b64 P1, [%0], %1, 0x989680;\n\t"
        "@P1 bra D_%=;\n\t"
        "bra W_%=;\n\t"
        "D_%=:\n\t}"
        :: "r"(mbar), "r"(ph) : "memory");
}
__device__ __forceinline__ void fence_proxy_async_cta() {
    asm volatile("fence.proxy.async.shared::cta;" ::: "memory");
}
__device__ __forceinline__ void tc_fence_after() {
    asm volatile("tcgen05.fence::after_thread_sync;" ::: "memory");
}
// cp.async (LDGSTS)
__device__ __forceinline__ void cp16(uint32_t dst, const void* src) {
    asm volatile("cp.async.cg.shared.global [%0], [%1], 16;" :: "r"(dst), "l"(src) : "memory");
}
__device__ __forceinline__ void cp4(uint32_t dst, const void* src) {
    asm volatile("cp.async.ca.shared.global [%0], [%1], 4;" :: "r"(dst), "l"(src) : "memory");
}
#define CP_COMMIT() asm volatile("cp.async.commit_group;" ::: "memory")
#define CP_WAIT(n)  asm volatile("cp.async.wait_group %0;" :: "n"(n) : "memory")

#define TC_ALLOC(dst, n)   asm volatile("tcgen05.alloc.cta_group::1.sync.aligned.shared::cta.b32 [%0], %1;" :: "r"(dst), "r"(n) : "memory")
#define TC_RELINQ()        asm volatile("tcgen05.relinquish_alloc_permit.cta_group::1.sync.aligned;")
#define TC_DEALLOC(t, n)   asm volatile("tcgen05.dealloc.cta_group::1.sync.aligned.b32 %0, %1;" :: "r"(t), "r"(n))
#define TC_WAIT_LD()       asm volatile("tcgen05.wait::ld.sync.aligned;" ::: "memory")
#define LDTM_X32(r, a) \
    asm volatile("tcgen05.ld.sync.aligned.32x32b.x32.b32 " \
        "{%0,%1,%2,%3,%4,%5,%6,%7,%8,%9,%10,%11,%12,%13,%14,%15," \
        "%16,%17,%18,%19,%20,%21,%22,%23,%24,%25,%26,%27,%28,%29,%30,%31}, [%32];" \
        : "=r"((r)[0]),"=r"((r)[1]),"=r"((r)[2]),"=r"((r)[3]),"=r"((r)[4]),"=r"((r)[5]),"=r"((r)[6]),"=r"((r)[7]), \
          "=r"((r)[8]),"=r"((r)[9]),"=r"((r)[10]),"=r"((r)[11]),"=r"((r)[12]),"=r"((r)[13]),"=r"((r)[14]),"=r"((r)[15]), \
          "=r"((r)[16]),"=r"((r)[17]),"=r"((r)[18]),"=r"((r)[19]),"=r"((r)[20]),"=r"((r)[21]),"=r"((r)[22]),"=r"((r)[23]), \
          "=r"((r)[24]),"=r"((r)[25]),"=r"((r)[26]),"=r"((r)[27]),"=r"((r)[28]),"=r"((r)[29]),"=r"((r)[30]),"=r"((r)[31]) \
        : "r"(a))

// MMA issue for one 128x512x32 tile (4 ksteps x 4 nchunks); commit -> mbar
__device__ __forceinline__ void issue_tile(uint32_t sb, uint32_t a_off, uint32_t b_off,
                                           uint32_t tmem, bool first, uint32_t mbar) {
    const uint64_t ab = make_desc(sb + a_off);
    const uint64_t bb = make_desc(sb + b_off);
    if (elect_one()) {
#pragma unroll
        for (int ks = 0; ks < 4; ++ks) {
            const uint32_t en = (!first || ks > 0) ? 1u : 0u;
#pragma unroll
            for (int nc = 0; nc < 4; ++nc)
                mma_tf32(tmem + nc * 128, ab + ks * 2, bb + nc * 1024 + ks * 2,
                         IDESC_TF32, en);
        }
        tc_commit(mbar);
    }
}

// Fused epilogue: y = D + resid + bias; LN(y) -> dst; optionally fq from cols 0..7.
__device__ __forceinline__ void epilogue_ln(char* sm, uint32_t tmem,
                                            const float* __restrict__ resid,
                                            float* __restrict__ dst, int bm, int t,
                                            bool do_fq, const float* __restrict__ thF) {
    const int w = t >> 5, lane = t & 31;
    const int sp = w & 3, half = w >> 2;
    const int row_local = sp * 32 + lane;
    const int grow = bm + row_local;
    const float* xr = resid + (size_t)grow * E_DIM;
    const float* bias = (const float*)(sm + SM_PAR);
    const float* gam  = (const float*)(sm + SM_PAR + 2048);
    const float* bet  = (const float*)(sm + SM_PAR + 4096);
    float* redp = (float*)(sm + SM_RED);

    // pass 1: stats
    float s = 0.f, ss = 0.f;
#pragma unroll 1
    for (int ch = 0; ch < 8; ++ch) {
        const int colb = half * 256 + ch * 32;
        uint32_t r[32];
        LDTM_X32(r, tmem + colb);
        TC_WAIT_LD();
#pragma unroll
        for (int c4 = 0; c4 < 8; ++c4) {
            const float4 xv = *(const float4*)(xr + colb + c4 * 4);
            const float4 bv = *(const float4*)(bias + colb + c4 * 4);
            float y0 = __uint_as_float(r[c4 * 4 + 0]) + xv.x + bv.x;
            float y1 = __uint_as_float(r[c4 * 4 + 1]) + xv.y + bv.y;
            float y2 = __uint_as_float(r[c4 * 4 + 2]) + xv.z + bv.z;
            float y3 = __uint_as_float(r[c4 * 4 + 3]) + xv.w + bv.w;
            s += y0 + y1 + y2 + y3;
            ss = fmaf(y0, y0, fmaf(y1, y1, fmaf(y2, y2, fmaf(y3, y3, ss))));
        }
    }
    redp[row_local * 2 + half] = s;
    redp[256 + row_local * 2 + half] = ss;
    __syncthreads();
    const float st  = redp[row_local * 2] + redp[row_local * 2 + 1];
    const float sst = redp[256 + row_local * 2] + redp[256 + row_local * 2 + 1];
    const float mu  = st * (1.0f / 512.0f);
    const float inv = rsqrtf(sst * (1.0f / 512.0f) - mu * mu + 1e-5f);

    // pass 2: normalize + store (coalesced via bounce)
    float* eb = (float*)(sm + SM_EP + w * 4608);  // [32][36]
    const int rbase = sp * 32;
#pragma unroll 1
    for (int ch = 0; ch < 8; ++ch) {
        const int colb = half * 256 + ch * 32;
        uint32_t r[32];
        LDTM_X32(r, tmem + colb);
        TC_WAIT_LD();
#pragma unroll
        for (int c4 = 0; c4 < 8; ++c4) {
            const float4 xv = *(const float4*)(xr + colb + c4 * 4);
            const float4 bv = *(const float4*)(bias + colb + c4 * 4);
            const float4 gv = *(const float4*)(gam + colb + c4 * 4);
            const float4 tv = *(const float4*)(bet + colb + c4 * 4);
            float4 o;
            o.x = (__uint_as_float(r[c4 * 4 + 0]) + xv.x + bv.x - mu) * inv * gv.x + tv.x;
            o.y = (__uint_as_float(r[c4 * 4 + 1]) + xv.y + bv.y - mu) * inv * gv.y + tv.y;
            o.z = (__uint_as_float(r[c4 * 4 + 2]) + xv.z + bv.z - mu) * inv * gv.z + tv.z;
            o.w = (__uint_as_float(r[c4 * 4 + 3]) + xv.w + bv.w - mu) * inv * gv.w + tv.w;
            *(float4*)(eb + lane * 36 + c4 * 4) = o;
        }
        if (do_fq && half == 0 && ch == 0) {
            const float4 o0 = *(const float4*)(eb + lane * 36);
            const float4 o1 = *(const float4*)(eb + lane * 36 + 4);
            float4 c0, c1;
            c0.x = cosf(o0.x + thF[0]); c0.y = cosf(o0.y + thF[1]);
            c0.z = cosf(o0.z + thF[2]); c0.w = cosf(o0.w + thF[3]);
            c1.x = cosf(o1.x + thF[4]); c1.y = cosf(o1.y + thF[5]);
            c1.z = cosf(o1.z + thF[6]); c1.w = cosf(o1.w + thF[7]);
            *(float4*)(g_fq + (size_t)grow * 8) = c0;
            *(float4*)(g_fq + (size_t)grow * 8 + 4) = c1;
        }
        __syncwarp();
#pragma unroll
        for (int j = 0; j < 32; ++j)
            dst[(size_t)(bm + rbase + j) * E_DIM + colb + lane] = eb[j * 36 + lane];
        __syncwarp();
    }
}
#endif  // HAS_TCGEN05

// ================= GEMM1 + LN1 fused (warp-specialized) =================
__global__ __launch_bounds__(256, 1)
void gemm1_tc(const float* __restrict__ x, const float* __restrict__ theta,
              const float* __restrict__ bc, const float* __restrict__ g1,
              const float* __restrict__ be1, const float* __restrict__ thF) {
#if HAS_TCGEN05
    extern __shared__ char sm[];
    const uint32_t sb = smem_u32(sm);
    const int t = threadIdx.x;
    const int bm = blockIdx.x * 128;

    if (t < 32) TC_ALLOC(sb + SM_TMEM, 512);
    if (t == 0) {
        mbar_init(sb + MB_FULL0, 224);  mbar_init(sb + MB_FULL1, 224);
        mbar_init(sb + MB_EMPTY0, 1);   mbar_init(sb + MB_EMPTY1, 1);
        mbar_init(sb + MB_FIN, 1);
    }
    ((float*)(sm + SM_PAR))[t] = bc[t];          ((float*)(sm + SM_PAR))[t + 256] = bc[t + 256];
    ((float*)(sm + SM_PAR + 2048))[t] = g1[t];   ((float*)(sm + SM_PAR + 2048))[t + 256] = g1[t + 256];
    ((float*)(sm + SM_PAR + 4096))[t] = be1[t];  ((float*)(sm + SM_PAR + 4096))[t + 256] = be1[t + 256];
    ((float*)(sm + SM_TH))[t] = theta[t];        ((float*)(sm + SM_TH))[t + 256] = theta[t + 256];
    __syncthreads();

    uint32_t tmem;
    asm volatile("ld.shared.b32 %0, [%1];" : "=r"(tmem) : "r"(sb + SM_TMEM));
    const float* th_s = (const float*)(sm + SM_TH);
    const char* bsrc = (const char*)g_Wcp;
    const int NIT = E_DIM / 32;  // 16

    if (t < 32) {
        // ---- MMA warp ----
        int phf[2] = {0, 0};
        for (int it = 0; it < NIT; ++it) {
            const int s = it & 1;
            mbar_wait(sb + MB_FULL0 + s * 8, phf[s]); phf[s] ^= 1;
            issue_tile(sb, s ? SM_A1 : SM_A0, s ? SM_B1 : SM_B0, tmem, it == 0,
                       sb + MB_EMPTY0 + s * 8);
        }
        if (elect_one()) tc_commit(sb + MB_FIN);
    } else {
        // ---- producers (224 threads) ----
        const int pt = t - 32;
        auto copy_stage = [&](int it, uint32_t Boff, uint32_t Xoff) {
            const char* bs = bsrc + (size_t)it * 65536;
            for (int g = pt; g < 4096; g += 224)
                cp16(sb + Boff + g * 16, bs + (size_t)g * 16);
            const int k0 = it * 32;
            for (int idx = pt; idx < 1024; idx += 224)
                cp16(sb + Xoff + idx * 16,
                     x + (size_t)(bm + (idx >> 3)) * E_DIM + k0 + (idx & 7) * 4);
            CP_COMMIT();
        };
        auto gen_A = [&](int it, uint32_t Aoff, uint32_t Xoff) {
            const int k0 = it * 32;
            for (int idx = pt; idx < 1024; idx += 224) {
                const int row = idx >> 3, q4 = idx & 7;
                const float4 v = *(const float4*)(sm + Xoff + idx * 16);
                const float4 thv = *(const float4*)(th_s + k0 + q4 * 4);
                uint4 o;
                o.x = f2tf32(cosf(v.x + thv.x));
                o.y = f2tf32(cosf(v.y + thv.y));
                o.z = f2tf32(cosf(v.z + thv.z));
                o.w = f2tf32(cosf(v.w + thv.w));
                *(uint4*)(sm + Aoff + swz_off(row, q4)) = o;
            }
        };

        copy_stage(0, SM_B0, SM_X0);
        CP_WAIT(0);
        gen_A(0, SM_A0, SM_X0);
        fence_proxy_async_cta();
        mbar_arrive(sb + MB_FULL0);
        copy_stage(1, SM_B1, SM_X1);

        int phe[2] = {0, 0};
        for (int it = 1; it < NIT; ++it) {
            const int s = it & 1;
            CP_WAIT(0);
            gen_A(it, s ? SM_A1 : SM_A0, s ? SM_X1 : SM_X0);
            fence_proxy_async_cta();
            mbar_arrive(sb + MB_FULL0 + s * 8);
            if (it + 1 < NIT) {
                const int s2 = (it + 1) & 1;
                mbar_wait(sb + MB_EMPTY0 + s2 * 8, phe[s2]); phe[s2] ^= 1;
                copy_stage(it + 1, s2 ? SM_B1 : SM_B0, s2 ? SM_X1 : SM_X0);
            }
        }
    }

    mbar_wait(sb + MB_FIN, 0);
    tc_fence_after();
    __syncthreads();

    epilogue_ln(sm, tmem, x, g_x1, bm, t, true, thF);

    __syncthreads();
    if (t < 32) { TC_RELINQ(); TC_DEALLOC(tmem, 512); }
#endif
}

// ================= GEMM2 + LN2 fused (warp-specialized) =================
__global__ __launch_bounds__(256, 1)
void gemm2_tc(const float* __restrict__ W1, const float* __restrict__ b1,
              const float* __restrict__ b2, const float* __restrict__ g2,
              const float* __restrict__ be2, float* __restrict__ out) {
#if HAS_TCGEN05
    extern __shared__ char sm[];
    const uint32_t sb = smem_u32(sm);
    const int t = threadIdx.x;
    const int bm = blockIdx.x * 128;

    if (t < 32) TC_ALLOC(sb + SM_TMEM, 512);
    if (t == 0) {
        mbar_init(sb + MB_FULL0, 224);  mbar_init(sb + MB_FULL1, 224);
        mbar_init(sb + MB_EMPTY0, 1);   mbar_init(sb + MB_EMPTY1, 1);
        mbar_init(sb + MB_FIN, 1);
    }
    ((float*)(sm + SM_PAR))[t] = b2[t];          ((float*)(sm + SM_PAR))[t + 256] = b2[t + 256];
    ((float*)(sm + SM_PAR + 2048))[t] = g2[t];   ((float*)(sm + SM_PAR + 2048))[t + 256] = g2[t + 256];
    ((float*)(sm + SM_PAR + 4096))[t] = be2[t];  ((float*)(sm + SM_PAR + 4096))[t + 256] = be2[t + 256];
    ((float4*)(sm + SM_TH))[t] = ((const float4*)(g_fq + (size_t)bm * 8))[t];  // fq 4KB
    __syncthreads();

    uint32_t tmem;
    asm volatile("ld.shared.b32 %0, [%1];" : "=r"(tmem) : "r"(sb + SM_TMEM));
    const char* bsrc = (const char*)g_W2p;
    const int NIT = FFN_DIM / 32;  // 64

    if (t < 32) {
        // ---- MMA warp ----
        int phf[2] = {0, 0};
        for (int it = 0; it < NIT; ++it) {
            const int s = it & 1;
            mbar_wait(sb + MB_FULL0 + s * 8, phf[s]); phf[s] ^= 1;
            issue_tile(sb, s ? SM_A1 : SM_A0, s ? SM_B1 : SM_B0, tmem, it == 0,
                       sb + MB_EMPTY0 + s * 8);
        }
        if (elect_one()) tc_commit(sb + MB_FIN);
    } else {
        // ---- producers (224 threads): pt = kl + 32*wg mapping ----
        const int pt = t - 32;
        const int kl = pt & 31;      // k column 0..31
        const int wg = pt >> 5;      // row group 0..6
        auto copy_stage = [&](int it, uint32_t Boff, uint32_t Woff) {
            const char* bs = bsrc + (size_t)it * 65536;
            for (int g = pt; g < 4096; g += 224)
                cp16(sb + Boff + g * 16, bs + (size_t)g * 16);
            const int k0 = it * 32;
            // each thread stages the W1 row + b1 element IT will read (7x dup, identical bytes)
            cp16(sb + Woff + kl * 32,      W1 + (size_t)(k0 + kl) * 8);
            cp16(sb + Woff + kl * 32 + 16, W1 + (size_t)(k0 + kl) * 8 + 4);
            cp4 (sb + Woff + 1024 + kl * 4, b1 + k0 + kl);
            CP_COMMIT();
        };
        auto gen_A = [&](uint32_t Aoff, uint32_t Woff) {
            const float4 w1a = *(const float4*)(sm + Woff + kl * 32);
            const float4 w1b = *(const float4*)(sm + Woff + kl * 32 + 16);
            const float b1v = *(const float*)(sm + Woff + 1024 + kl * 4);
            for (int r = wg; r < 128; r += 7) {
                const float4 f0 = *(const float4*)(sm + SM_TH + r * 32);
                const float4 f1 = *(const float4*)(sm + SM_TH + r * 32 + 16);
                float h = b1v;
                h = fmaf(f0.x, w1a.x, h); h = fmaf(f0.y, w1a.y, h);
                h = fmaf(f0.z, w1a.z, h); h = fmaf(f0.w, w1a.w, h);
                h = fmaf(f1.x, w1b.x, h); h = fmaf(f1.y, w1b.y, h);
                h = fmaf(f1.z, w1b.z, h); h = fmaf(f1.w, w1b.w, h);
                h = fmaxf(h, 0.0f);
                *(uint32_t*)(sm + Aoff + (uint32_t)(r * 128 + (((kl >> 2) ^ (r & 7)) * 16 + (kl & 3) * 4))) = f2tf32(h);
            }
        };

        copy_stage(0, SM_B0, SM_W1A);
        CP_WAIT(0);
        gen_A(SM_A0, SM_W1A);
        fence_proxy_async_cta();
        mbar_arrive(sb + MB_FULL0);
        copy_stage(1, SM_B1, SM_W1B);

        int phe[2] = {0, 0};
        for (int it = 1; it < NIT; ++it) {
            const int s = it & 1;
            CP_WAIT(0);
            gen_A(s ? SM_A1 : SM_A0, s ? SM_W1B : SM_W1A);
            fence_proxy_async_cta();
            mbar_arrive(sb + MB_FULL0 + s * 8);
            if (it + 1 < NIT) {
                const int s2 = (it + 1) & 1;
                mbar_wait(sb + MB_EMPTY0 + s2 * 8, phe[s2]); phe[s2] ^= 1;
                copy_stage(it + 1, s2 ? SM_B1 : SM_B0, s2 ? SM_W1B : SM_W1A);
            }
        }
    }

    mbar_wait(sb + MB_FIN, 0);
    tc_fence_after();
    __syncthreads();

    epilogue_ln(sm, tmem, g_x1, out, bm, t, false, nullptr);

    __syncthreads();
    if (t < 32) { TC_RELINQ(); TC_DEALLOC(tmem, 512); }
#endif
}

// ================= launch =================
extern "C" void kernel_launch(void* const* d_in, const int* in_sizes, int n_in,
                              void* d_out, int out_size) {
    const float* x   = (const float*)d_in[0];
    const float* thA = (const float*)d_in[1];
    const float* Wc  = (const float*)d_in[2];
    const float* bc  = (const float*)d_in[3];
    const float* g1  = (const float*)d_in[4];
    const float* be1 = (const float*)d_in[5];
    const float* thF = (const float*)d_in[6];
    const float* W1  = (const float*)d_in[7];
    const float* b1  = (const float*)d_in[8];
    const float* W2  = (const float*)d_in[9];
    const float* b2  = (const float*)d_in[10];
    const float* g2  = (const float*)d_in[11];
    const float* be2 = (const float*)d_in[12];
    float* out = (float*)d_out;

    cudaFuncSetAttribute(gemm1_tc, cudaFuncAttributeMaxDynamicSharedMemorySize, SMEM_BYTES);
    cudaFuncSetAttribute(gemm2_tc, cudaFuncAttributeMaxDynamicSharedMemorySize, SMEM_BYTES);

    repack_kernel<<<(512 * E_DIM / 4 + 255) / 256, 256>>>(Wc, E_DIM, 0);
    repack_kernel<<<(512 * FFN_DIM / 4 + 255) / 256, 256>>>(W2, FFN_DIM, 1);

    gemm1_tc<<<M_TOTAL / 128, 256, SMEM_BYTES>>>(x, thA, bc, g1, be1, thF);
    gemm2_tc<<<M_TOTAL / 128, 256, SMEM_BYTES>>>(W1, b1, b2, g2, be2, out);
}